// round 9
// baseline (speedup 1.0000x reference)
#include <cuda_runtime.h>
#include <cstdint>

#define BB 32
#define NN 4096
#define DU 64
#define DD 128
#define TILES 8
#define CHUNKS 4
#define NBLK (BB*CHUNKS)     // 128 blocks, single wave

// shared-memory layout (float offsets)
#define W1_O 0                       // [64][132]
#define W2_O (W1_O + 64*132)         // [128][132]
#define U_O  (W2_O + 128*132)        // [128][68]
#define Z_O  (U_O  + 128*68)         // [128][132]  (Z1 then Z, aliased; wv + tail scratch)
#define B1_O (Z_O  + 128*132)
#define B2_O (B1_O + 128)
#define SS_O (B2_O + 128)
#define SQF_O (SS_O + 128)
#define SA0_O (SQF_O + 128)
#define SA1_O (SA0_O + 128)
#define SV_O  (SA1_O + 128)          // 256 floats: v0[128], v1[128]
#define FLAG_O (SV_O + 256)
#define SMEM_FLOATS (FLAG_O + 4)
#define SMEM_BYTES (SMEM_FLOATS * 4) // ~208 KB

__device__ float g_partV[NBLK][256];   // per-block a^T G partials (2 heads x 128)
__device__ float g_partS[NBLK][DD];
__device__ float g_C0[DD*DD];          // C_0[q][j] = sum_{t<64}  Wv[q][t] Wo[t][j]
__device__ float g_C1[DD*DD];          // C_1[q][j] = sum_{t>=64} Wv[q][t] Wo[t][j]
__device__ unsigned g_ctr = 0;         // wraps back to 0 every full run

static __device__ __forceinline__ uint32_t tf32r(float f) {
    uint32_t r; asm("cvt.rna.tf32.f32 %0, %1;" : "=r"(r) : "f"(f)); return r;
}
static __device__ __forceinline__ float tf32f(float f) {
    return __uint_as_float(tf32r(f));
}
// jax.nn.gelu approximate
static __device__ __forceinline__ float gelu_f(float x) {
    float x2 = x * x;
    float y2 = x * fmaf(0.0713548162f, x2, 1.5957691216f);
    float e  = __expf(y2);
    return x - __fdividef(x, e + 1.0f);
}
// m16n8k8 tf32 HMMA, D = A*B + D
static __device__ __forceinline__ void mma8(float* c, const uint32_t* a, const uint32_t* b) {
    asm volatile(
        "mma.sync.aligned.m16n8k8.row.col.f32.tf32.tf32.f32 "
        "{%0,%1,%2,%3},{%4,%5,%6,%7},{%8,%9},{%0,%1,%2,%3};"
        : "+f"(c[0]), "+f"(c[1]), "+f"(c[2]), "+f"(c[3])
        : "r"(a[0]), "r"(a[1]), "r"(a[2]), "r"(a[3]), "r"(b[0]), "r"(b[1]));
}

// ================= single fused kernel =================
__global__ void __launch_bounds__(256, 1)
fused_all_kernel(const float* __restrict__ u,
                 const float* __restrict__ W1, const float* __restrict__ b1,
                 const float* __restrict__ W2, const float* __restrict__ b2,
                 const float* __restrict__ embed,
                 const float* __restrict__ Wq, const float* __restrict__ bq,
                 const float* __restrict__ Wk, const float* __restrict__ bk,
                 const float* __restrict__ Wv, const float* __restrict__ bv,
                 const float* __restrict__ Wo, const float* __restrict__ bo,
                 float* __restrict__ out)
{
    extern __shared__ float sm[];
    const int tid  = threadIdx.x;
    const int w    = tid >> 5;
    const int lane = tid & 31;
    const int lr   = lane >> 2;      // fragment row group 0..7
    const int lc   = lane & 3;       // fragment k group 0..3
    const int mb   = (w >> 1) * 32;  // warp row base
    const int nb   = (w & 1) * 64;   // warp col base
    const int bid  = blockIdx.x;

    // ---- stage weights as tf32 ----
    for (int i = tid; i < 64 * 128; i += 256) {
        int k = i >> 7, n = i & 127;
        sm[W1_O + k * 132 + n] = tf32f(W1[i]);
    }
    for (int i = tid; i < 128 * 128; i += 256) {
        int k = i >> 7, n = i & 127;
        sm[W2_O + k * 132 + n] = tf32f(W2[i]);
    }
    if (tid < 128) {
        sm[B1_O + tid] = b1[tid]; sm[B2_O + tid] = b2[tid];
        sm[SS_O + tid] = 0.f;
        sm[SV_O + tid] = 0.f; sm[SV_O + 128 + tid] = 0.f;
        // qf[t] = embed @ Wq + bq  (identical across blocks)
        float acc = bq[tid];
#pragma unroll 8
        for (int p = 0; p < DD; p++) acc = fmaf(embed[p], Wq[p * DD + tid], acc);
        sm[SQF_O + tid] = acc;
    }

    float g[2][8][4];     // Gram accumulators
#pragma unroll
    for (int mt = 0; mt < 2; mt++)
#pragma unroll
        for (int nt = 0; nt < 8; nt++)
#pragma unroll
            for (int i = 0; i < 4; i++) g[mt][nt][i] = 0.f;
    float sacc[16];
#pragma unroll
    for (int i = 0; i < 16; i++) sacc[i] = 0.f;

    const float* ub = u + ((size_t)(bid >> 2) * NN + (size_t)(bid & 3) * 1024) * DU;

    __syncthreads();

    // a_h[p] = sum_d qf[h*64+d] * Wk[p][h*64+d]
    if (tid < 128) {
        float a0 = 0.f, a1 = 0.f;
#pragma unroll 8
        for (int d = 0; d < 64; d++) {
            a0 = fmaf(sm[SQF_O + d],      Wk[tid * DD + d],      a0);
            a1 = fmaf(sm[SQF_O + 64 + d], Wk[tid * DD + 64 + d], a1);
        }
        sm[SA0_O + tid] = a0; sm[SA1_O + tid] = a1;
        // stage this block's Wv row for the C-row precompute (Z_O scratch, free until epilogue1)
        sm[Z_O + tid] = Wv[bid * DD + tid];
    }

    float b1r[16], b2r[16];
#pragma unroll
    for (int nt = 0; nt < 8; nt++) {
        int col = nb + nt * 8 + 2 * lc;
        b1r[nt * 2] = sm[B1_O + col]; b1r[nt * 2 + 1] = sm[B1_O + col + 1];
        b2r[nt * 2] = sm[B2_O + col]; b2r[nt * 2 + 1] = sm[B2_O + col + 1];
    }

    // prefetch tile 0 into registers
    float4 pref[8];
    {
        const float4* uv = (const float4*)ub;
#pragma unroll
        for (int i = 0; i < 8; i++) pref[i] = uv[i * 256 + tid];
    }
    __syncthreads();

    // ---- fold of precompute: block bid computes row bid of C0/C1 ----
    {
        const int j = tid & 127;
        const int hh = tid >> 7;                 // 0 -> C0 (t<64), 1 -> C1 (t>=64)
        const float* wv = &sm[Z_O + hh * 64];
        const float* wo = Wo + (size_t)hh * 64 * DD + j;
        float c = 0.f;
#pragma unroll 16
        for (int t = 0; t < 64; t++) c = fmaf(wv[t], wo[t * DD], c);
        if (hh == 0) g_C0[bid * DD + j] = c;
        else         g_C1[bid * DD + j] = c;
    }

    for (int tt = 0; tt < TILES; tt++) {
        // ---- store prefetched U tile (tf32, pitch 68), then prefetch next ----
#pragma unroll
        for (int i = 0; i < 8; i++) {
            int idx = i * 256 + tid;
            int tok = idx >> 4, kq = idx & 15;
            float4 f = pref[i];
            *(float4*)&sm[U_O + tok * 68 + kq * 4] =
                make_float4(tf32f(f.x), tf32f(f.y), tf32f(f.z), tf32f(f.w));
        }
        if (tt + 1 < TILES) {
            const float4* uv = (const float4*)(ub + (size_t)(tt + 1) * 128 * DU);
#pragma unroll
            for (int i = 0; i < 8; i++) pref[i] = uv[i * 256 + tid];
        }
        __syncthreads();

        float c[2][8][4];

        // ======== MLP1: C = U @ W1  (K=64) ========
#pragma unroll
        for (int mt = 0; mt < 2; mt++)
#pragma unroll
            for (int nt = 0; nt < 8; nt++)
#pragma unroll
                for (int i = 0; i < 4; i++) c[mt][nt][i] = 0.f;
        {
            const float* As = &sm[U_O + (mb + lr) * 68 + lc];
            const float* Bs = &sm[W1_O + lc * 132 + nb + lr];
#pragma unroll 4
            for (int kt = 0; kt < 8; kt++) {
                uint32_t a[2][4], bf[8][2];
#pragma unroll
                for (int mt = 0; mt < 2; mt++) {
                    const float* p = As + mt * 16 * 68 + kt * 8;
                    a[mt][0] = __float_as_uint(p[0]);
                    a[mt][1] = __float_as_uint(p[8 * 68]);
                    a[mt][2] = __float_as_uint(p[4]);
                    a[mt][3] = __float_as_uint(p[8 * 68 + 4]);
                }
#pragma unroll
                for (int nt = 0; nt < 8; nt++) {
                    const float* p = Bs + kt * 8 * 132 + nt * 8;
                    bf[nt][0] = __float_as_uint(p[0]);
                    bf[nt][1] = __float_as_uint(p[4 * 132]);
                }
#pragma unroll
                for (int mt = 0; mt < 2; mt++)
#pragma unroll
                    for (int nt = 0; nt < 8; nt++) mma8(c[mt][nt], a[mt], bf[nt]);
            }
        }
        __syncthreads();

        // epilogue 1: Z1 = gelu(C + b1)
#pragma unroll
        for (int mt = 0; mt < 2; mt++)
#pragma unroll
            for (int nt = 0; nt < 8; nt++) {
                int row = mb + mt * 16 + lr;
                int col = nb + nt * 8 + 2 * lc;
                float z0 = gelu_f(c[mt][nt][0] + b1r[nt * 2]);
                float z1 = gelu_f(c[mt][nt][1] + b1r[nt * 2 + 1]);
                float z2 = gelu_f(c[mt][nt][2] + b1r[nt * 2]);
                float z3 = gelu_f(c[mt][nt][3] + b1r[nt * 2 + 1]);
                *(float2*)&sm[Z_O + row * 132 + col]       = make_float2(tf32f(z0), tf32f(z1));
                *(float2*)&sm[Z_O + (row + 8) * 132 + col] = make_float2(tf32f(z2), tf32f(z3));
            }
        __syncthreads();

        // ======== MLP2: C = Z1 @ W2  (K=128) ========
#pragma unroll
        for (int mt = 0; mt < 2; mt++)
#pragma unroll
            for (int nt = 0; nt < 8; nt++)
#pragma unroll
                for (int i = 0; i < 4; i++) c[mt][nt][i] = 0.f;
        {
            const float* As = &sm[Z_O + (mb + lr) * 132 + lc];
            const float* Bs = &sm[W2_O + lc * 132 + nb + lr];
#pragma unroll 4
            for (int kt = 0; kt < 16; kt++) {
                uint32_t a[2][4], bf[8][2];
#pragma unroll
                for (int mt = 0; mt < 2; mt++) {
                    const float* p = As + mt * 16 * 132 + kt * 8;
                    a[mt][0] = __float_as_uint(p[0]);
                    a[mt][1] = __float_as_uint(p[8 * 132]);
                    a[mt][2] = __float_as_uint(p[4]);
                    a[mt][3] = __float_as_uint(p[8 * 132 + 4]);
                }
#pragma unroll
                for (int nt = 0; nt < 8; nt++) {
                    const float* p = Bs + kt * 8 * 132 + nt * 8;
                    bf[nt][0] = __float_as_uint(p[0]);
                    bf[nt][1] = __float_as_uint(p[4 * 132]);
                }
#pragma unroll
                for (int mt = 0; mt < 2; mt++)
#pragma unroll
                    for (int nt = 0; nt < 8; nt++) mma8(c[mt][nt], a[mt], bf[nt]);
            }
        }
        __syncthreads();

        // epilogue 2: Z = gelu(C + b2); S += columns
#pragma unroll
        for (int mt = 0; mt < 2; mt++)
#pragma unroll
            for (int nt = 0; nt < 8; nt++) {
                int row = mb + mt * 16 + lr;
                int col = nb + nt * 8 + 2 * lc;
                float z0 = gelu_f(c[mt][nt][0] + b2r[nt * 2]);
                float z1 = gelu_f(c[mt][nt][1] + b2r[nt * 2 + 1]);
                float z2 = gelu_f(c[mt][nt][2] + b2r[nt * 2]);
                float z3 = gelu_f(c[mt][nt][3] + b2r[nt * 2 + 1]);
                sacc[nt * 2]     += z0 + z2;
                sacc[nt * 2 + 1] += z1 + z3;
                *(float2*)&sm[Z_O + row * 132 + col]       = make_float2(tf32f(z0), tf32f(z1));
                *(float2*)&sm[Z_O + (row + 8) * 132 + col] = make_float2(tf32f(z2), tf32f(z3));
            }
        __syncthreads();

        // ======== Gram: G += Z^T @ Z ========
        {
#pragma unroll 4
            for (int kt = 0; kt < 16; kt++) {
                uint32_t a[2][4], bf[8][2];
                const float* At = &sm[Z_O + (kt * 8 + lc) * 132 + mb + lr];
#pragma unroll
                for (int mt = 0; mt < 2; mt++) {
                    const float* p = At + mt * 16;
                    a[mt][0] = __float_as_uint(p[0]);
                    a[mt][1] = __float_as_uint(p[8]);
                    a[mt][2] = __float_as_uint(p[4 * 132]);
                    a[mt][3] = __float_as_uint(p[4 * 132 + 8]);
                }
                const float* Bt = &sm[Z_O + (kt * 8 + lc) * 132 + nb + lr];
#pragma unroll
                for (int nt = 0; nt < 8; nt++) {
                    const float* p = Bt + nt * 8;
                    bf[nt][0] = __float_as_uint(p[0]);
                    bf[nt][1] = __float_as_uint(p[4 * 132]);
                }
#pragma unroll
                for (int mt = 0; mt < 2; mt++)
#pragma unroll
                    for (int nt = 0; nt < 8; nt++) mma8(g[mt][nt], a[mt], bf[nt]);
            }
        }
        __syncthreads();
    }

    // ---- contract G with a_h in-register: v_h[col] = sum_rows a_h[row]*G[row][col] ----
    {
        float ar0[2][2], ar1[2][2];
#pragma unroll
        for (int mt = 0; mt < 2; mt++) {
            int row = mb + mt * 16 + lr;
            ar0[mt][0] = sm[SA0_O + row];     ar0[mt][1] = sm[SA0_O + row + 8];
            ar1[mt][0] = sm[SA1_O + row];     ar1[mt][1] = sm[SA1_O + row + 8];
        }
        float v0[16], v1[16];
#pragma unroll
        for (int nt = 0; nt < 8; nt++)
#pragma unroll
            for (int j = 0; j < 2; j++) {
                float s0 = 0.f, s1 = 0.f;
#pragma unroll
                for (int mt = 0; mt < 2; mt++) {
                    s0 = fmaf(ar0[mt][0], g[mt][nt][j],     s0);
                    s0 = fmaf(ar0[mt][1], g[mt][nt][2 + j], s0);
                    s1 = fmaf(ar1[mt][0], g[mt][nt][j],     s1);
                    s1 = fmaf(ar1[mt][1], g[mt][nt][2 + j], s1);
                }
                v0[nt * 2 + j] = s0; v1[nt * 2 + j] = s1;
            }
#pragma unroll
        for (int i = 0; i < 16; i++) {
            v0[i] += __shfl_down_sync(0xFFFFFFFFu, v0[i], 16);
            v0[i] += __shfl_down_sync(0xFFFFFFFFu, v0[i], 8);
            v0[i] += __shfl_down_sync(0xFFFFFFFFu, v0[i], 4);
            v1[i] += __shfl_down_sync(0xFFFFFFFFu, v1[i], 16);
            v1[i] += __shfl_down_sync(0xFFFFFFFFu, v1[i], 8);
            v1[i] += __shfl_down_sync(0xFFFFFFFFu, v1[i], 4);
        }
        if (lr == 0) {
#pragma unroll
            for (int i = 0; i < 16; i++) {
                int col = nb + (i >> 1) * 8 + 2 * lc + (i & 1);
                atomicAdd(&sm[SV_O + col],       v0[i]);
                atomicAdd(&sm[SV_O + 128 + col], v1[i]);
            }
        }
    }

    // ---- reduce S ----
#pragma unroll
    for (int i = 0; i < 16; i++) {
        float v = sacc[i];
        v += __shfl_down_sync(0xFFFFFFFFu, v, 16);
        v += __shfl_down_sync(0xFFFFFFFFu, v, 8);
        v += __shfl_down_sync(0xFFFFFFFFu, v, 4);
        if (lr == 0) atomicAdd(&sm[SS_O + nb + (i >> 1) * 8 + 2 * lc + (i & 1)], v);
    }
    __syncthreads();
    if (tid < 128) g_partS[bid][tid] = sm[SS_O + tid];
    g_partV[bid][tid] = sm[SV_O + tid];

    // ---- last-block-done: fold the tail in ----
    __threadfence();
    __syncthreads();
    if (tid == 0) {
        unsigned old = atomicInc(&g_ctr, NBLK - 1);   // wraps to 0 after full run
        sm[FLAG_O] = (old == NBLK - 1) ? 1.0f : 0.0f;
    }
    __syncthreads();
    if (sm[FLAG_O] != 0.0f) {
        __threadfence();
        const int j  = tid & 127;
        const int hh = tid >> 7;
        // scratch in U_O region (free now)
        float* e0  = &sm[U_O];
        float* e1  = e0 + 128;
        float* sS  = e1 + 128;        // [2][128]
        float* sW0 = sS + 256;        // [2][128]
        float* sW1 = sW0 + 256;       // [2][128]

        // e_h[j] = sum_{t in h} bv[t] * Wo[t][j]
        {
            const float* wo = Wo + (size_t)hh * 64 * DD + j;
            const float* bvh = bv + hh * 64;
            float e = 0.f;
#pragma unroll 16
            for (int t = 0; t < 64; t++) e = fmaf(bvh[t], wo[t * DD], e);
            if (hh == 0) e0[j] = e; else e1[j] = e;
        }
        // qbk_h = qf_h . bk_h  (redundant per-thread; qf still in smem)
        float qbk0 = 0.f, qbk1 = 0.f;
#pragma unroll 16
        for (int d = 0; d < 64; d++) {
            qbk0 = fmaf(sm[SQF_O + d],      bk[d],      qbk0);
            qbk1 = fmaf(sm[SQF_O + 64 + d], bk[64 + d], qbk1);
        }
        __syncthreads();

        for (int it = 0; it < 16; it++) {
            const int b = it * 2 + hh;
            float s = 0.f, v0 = 0.f, v1 = 0.f;
#pragma unroll
            for (int cc = 0; cc < 4; cc++) {
                s  += g_partS[b * 4 + cc][j];
                v0 += g_partV[b * 4 + cc][j];
                v1 += g_partV[b * 4 + cc][128 + j];
            }
            sS[hh * 128 + j]  = s;
            sW0[hh * 128 + j] = v0 + qbk0 * s;
            sW1[hh * 128 + j] = v1 + qbk1 * s;
            __syncthreads();

            float asd0 = 0.f, asd1 = 0.f;
#pragma unroll 16
            for (int q = 0; q < DD; q++) {
                float sv = sS[hh * 128 + q];
                asd0 = fmaf(sm[SA0_O + q], sv, asd0);
                asd1 = fmaf(sm[SA1_O + q], sv, asd1);
            }
            float acc = 0.f;
#pragma unroll 8
            for (int q = 0; q < DD; q++) {
                acc = fmaf(sW0[hh * 128 + q], g_C0[q * DD + j], acc);
                acc = fmaf(sW1[hh * 128 + q], g_C1[q * DD + j], acc);
            }
            acc += (asd0 + (float)NN * qbk0) * e0[j];
            acc += (asd1 + (float)NN * qbk1) * e1[j];
            out[b * DD + j] = bo[j] + acc * (1.0f / (float)NN);
            __syncthreads();
        }
    }
}

// ================= launch =================
extern "C" void kernel_launch(void* const* d_in, const int* in_sizes, int n_in,
                              void* d_out, int out_size)
{
    const float* u     = (const float*)d_in[0];
    const float* W1    = (const float*)d_in[2];
    const float* b1    = (const float*)d_in[3];
    const float* W2    = (const float*)d_in[4];
    const float* b2    = (const float*)d_in[5];
    const float* embed = (const float*)d_in[6];
    const float* Wq    = (const float*)d_in[7];
    const float* bq    = (const float*)d_in[8];
    const float* Wk    = (const float*)d_in[9];
    const float* bk    = (const float*)d_in[10];
    const float* Wv    = (const float*)d_in[11];
    const float* bv    = (const float*)d_in[12];
    const float* Wo    = (const float*)d_in[13];
    const float* bo    = (const float*)d_in[14];
    float* out = (float*)d_out;

    cudaFuncSetAttribute(fused_all_kernel,
                         cudaFuncAttributeMaxDynamicSharedMemorySize, SMEM_BYTES);

    fused_all_kernel<<<NBLK, 256, SMEM_BYTES>>>(u, W1, b1, W2, b2, embed,
                                                Wq, bq, Wk, bk, Wv, bv, Wo, bo, out);
}

// round 10
// speedup vs baseline: 1.6785x; 1.6785x over previous
#include <cuda_runtime.h>
#include <cstdint>

#define BB 32
#define NN 4096
#define DU 64
#define DD 128
#define TILES 8
#define CHUNKS 4
#define NBLK (BB*CHUNKS)     // 128 blocks, single wave

// shared-memory layout (float offsets)
#define W1_O 0                       // [64][132]
#define W2_O (W1_O + 64*132)         // [128][132]
#define U_O  (W2_O + 128*132)        // [128][68]
#define Z_O  (U_O  + 128*68)         // [128][132]  (Z1 then Z, aliased)
#define B1_O (Z_O  + 128*132)
#define B2_O (B1_O + 128)
#define SS_O (B2_O + 128)
#define SQF_O (SS_O + 128)
#define SA0_O (SQF_O + 128)
#define SA1_O (SA0_O + 128)
#define SV_O  (SA1_O + 128)          // 256 floats: v0[128], v1[128]
#define SMEM_FLOATS (SV_O + 256)
#define SMEM_BYTES (SMEM_FLOATS * 4) // ~207.9 KB

__device__ float g_partV[NBLK][256];   // per-block a^T G partials (2 heads x 128)
__device__ float g_partS[NBLK][DD];
__device__ float g_a0[DD], g_a1[DD];   // a_h = Wk^T qf (written by block 0)
__device__ float g_qbk[2];             // qf_h . bk_h  (written by block 0)

static __device__ __forceinline__ uint32_t tf32r(float f) {
    uint32_t r; asm("cvt.rna.tf32.f32 %0, %1;" : "=r"(r) : "f"(f)); return r;
}
static __device__ __forceinline__ float tf32f(float f) {
    return __uint_as_float(tf32r(f));
}
// jax.nn.gelu approximate
static __device__ __forceinline__ float gelu_f(float x) {
    float x2 = x * x;
    float y2 = x * fmaf(0.0713548162f, x2, 1.5957691216f);
    float e  = __expf(y2);
    return x - __fdividef(x, e + 1.0f);
}
// m16n8k8 tf32 HMMA, D = A*B + D
static __device__ __forceinline__ void mma8(float* c, const uint32_t* a, const uint32_t* b) {
    asm volatile(
        "mma.sync.aligned.m16n8k8.row.col.f32.tf32.tf32.f32 "
        "{%0,%1,%2,%3},{%4,%5,%6,%7},{%8,%9},{%0,%1,%2,%3};"
        : "+f"(c[0]), "+f"(c[1]), "+f"(c[2]), "+f"(c[3])
        : "r"(a[0]), "r"(a[1]), "r"(a[2]), "r"(a[3]), "r"(b[0]), "r"(b[1]));
}

// ================= main fused kernel =================
__global__ void __launch_bounds__(256, 1)
fused_mma_kernel(const float* __restrict__ u,
                 const float* __restrict__ W1, const float* __restrict__ b1,
                 const float* __restrict__ W2, const float* __restrict__ b2,
                 const float* __restrict__ embed,
                 const float* __restrict__ Wq, const float* __restrict__ bq,
                 const float* __restrict__ Wk, const float* __restrict__ bk)
{
    extern __shared__ float sm[];
    const int tid  = threadIdx.x;
    const int w    = tid >> 5;
    const int lane = tid & 31;
    const int lr   = lane >> 2;      // fragment row group 0..7
    const int lc   = lane & 3;       // fragment k group 0..3
    const int mb   = (w >> 1) * 32;  // warp row base
    const int nb   = (w & 1) * 64;   // warp col base
    const int bid  = blockIdx.x;

    // ---- stage weights as tf32 ----
    for (int i = tid; i < 64 * 128; i += 256) {
        int k = i >> 7, n = i & 127;
        sm[W1_O + k * 132 + n] = tf32f(W1[i]);
    }
    for (int i = tid; i < 128 * 128; i += 256) {
        int k = i >> 7, n = i & 127;
        sm[W2_O + k * 132 + n] = tf32f(W2[i]);
    }
    if (tid < 128) {
        sm[B1_O + tid] = b1[tid]; sm[B2_O + tid] = b2[tid];
        sm[SS_O + tid] = 0.f;
        sm[SV_O + tid] = 0.f; sm[SV_O + 128 + tid] = 0.f;
        // qf[t] = embed @ Wq + bq  (identical across blocks)
        float acc = bq[tid];
#pragma unroll 8
        for (int p = 0; p < DD; p++) acc = fmaf(embed[p], Wq[p * DD + tid], acc);
        sm[SQF_O + tid] = acc;
    }

    float g[2][8][4];     // Gram accumulators
#pragma unroll
    for (int mt = 0; mt < 2; mt++)
#pragma unroll
        for (int nt = 0; nt < 8; nt++)
#pragma unroll
            for (int i = 0; i < 4; i++) g[mt][nt][i] = 0.f;
    float sacc[16];
#pragma unroll
    for (int i = 0; i < 16; i++) sacc[i] = 0.f;

    const float* ub = u + ((size_t)(bid >> 2) * NN + (size_t)(bid & 3) * 1024) * DU;

    __syncthreads();

    // a_h[p] = sum_d qf[h*64+d] * Wk[p][h*64+d]
    if (tid < 128) {
        float a0 = 0.f, a1 = 0.f;
#pragma unroll 8
        for (int d = 0; d < 64; d++) {
            a0 = fmaf(sm[SQF_O + d],      Wk[tid * DD + d],      a0);
            a1 = fmaf(sm[SQF_O + 64 + d], Wk[tid * DD + 64 + d], a1);
        }
        sm[SA0_O + tid] = a0; sm[SA1_O + tid] = a1;
        if (bid == 0) {
            g_a0[tid] = a0; g_a1[tid] = a1;
            if (tid < 2) {
                float s = 0.f;
#pragma unroll 8
                for (int d = 0; d < 64; d++)
                    s = fmaf(sm[SQF_O + tid * 64 + d], bk[tid * 64 + d], s);
                g_qbk[tid] = s;
            }
        }
    }

    for (int tt = 0; tt < TILES; tt++) {
        // ---- load U tile (128 tok x 64) direct to smem as tf32, pitch 68 ----
        {
            const float4* uv = (const float4*)(ub + (size_t)tt * 128 * DU);
#pragma unroll
            for (int i = 0; i < 8; i++) {
                int idx = i * 256 + tid;
                int tok = idx >> 4, kq = idx & 15;
                float4 f = uv[idx];
                *(float4*)&sm[U_O + tok * 68 + kq * 4] =
                    make_float4(tf32f(f.x), tf32f(f.y), tf32f(f.z), tf32f(f.w));
            }
        }
        __syncthreads();

        float c[2][8][4];

        // ======== MLP1: C = U @ W1  (K=64) ========
#pragma unroll
        for (int mt = 0; mt < 2; mt++)
#pragma unroll
            for (int nt = 0; nt < 8; nt++)
#pragma unroll
                for (int i = 0; i < 4; i++) c[mt][nt][i] = 0.f;
        {
            const float* As = &sm[U_O + (mb + lr) * 68 + lc];
            const float* Bs = &sm[W1_O + lc * 132 + nb + lr];
#pragma unroll 4
            for (int kt = 0; kt < 8; kt++) {
                uint32_t a[2][4], bf[8][2];
#pragma unroll
                for (int mt = 0; mt < 2; mt++) {
                    const float* p = As + mt * 16 * 68 + kt * 8;
                    a[mt][0] = __float_as_uint(p[0]);
                    a[mt][1] = __float_as_uint(p[8 * 68]);
                    a[mt][2] = __float_as_uint(p[4]);
                    a[mt][3] = __float_as_uint(p[8 * 68 + 4]);
                }
#pragma unroll
                for (int nt = 0; nt < 8; nt++) {
                    const float* p = Bs + kt * 8 * 132 + nt * 8;
                    bf[nt][0] = __float_as_uint(p[0]);
                    bf[nt][1] = __float_as_uint(p[4 * 132]);
                }
#pragma unroll
                for (int mt = 0; mt < 2; mt++)
#pragma unroll
                    for (int nt = 0; nt < 8; nt++) mma8(c[mt][nt], a[mt], bf[nt]);
            }
        }
        __syncthreads();

        // epilogue 1: Z1 = gelu(C + b1)   (biases via smem broadcast)
#pragma unroll
        for (int mt = 0; mt < 2; mt++)
#pragma unroll
            for (int nt = 0; nt < 8; nt++) {
                int row = mb + mt * 16 + lr;
                int col = nb + nt * 8 + 2 * lc;
                float bb0 = sm[B1_O + col], bb1 = sm[B1_O + col + 1];
                float z0 = gelu_f(c[mt][nt][0] + bb0);
                float z1 = gelu_f(c[mt][nt][1] + bb1);
                float z2 = gelu_f(c[mt][nt][2] + bb0);
                float z3 = gelu_f(c[mt][nt][3] + bb1);
                *(float2*)&sm[Z_O + row * 132 + col]       = make_float2(tf32f(z0), tf32f(z1));
                *(float2*)&sm[Z_O + (row + 8) * 132 + col] = make_float2(tf32f(z2), tf32f(z3));
            }
        __syncthreads();

        // ======== MLP2: C = Z1 @ W2  (K=128) ========
#pragma unroll
        for (int mt = 0; mt < 2; mt++)
#pragma unroll
            for (int nt = 0; nt < 8; nt++)
#pragma unroll
                for (int i = 0; i < 4; i++) c[mt][nt][i] = 0.f;
        {
            const float* As = &sm[Z_O + (mb + lr) * 132 + lc];
            const float* Bs = &sm[W2_O + lc * 132 + nb + lr];
#pragma unroll 4
            for (int kt = 0; kt < 16; kt++) {
                uint32_t a[2][4], bf[8][2];
#pragma unroll
                for (int mt = 0; mt < 2; mt++) {
                    const float* p = As + mt * 16 * 132 + kt * 8;
                    a[mt][0] = __float_as_uint(p[0]);
                    a[mt][1] = __float_as_uint(p[8 * 132]);
                    a[mt][2] = __float_as_uint(p[4]);
                    a[mt][3] = __float_as_uint(p[8 * 132 + 4]);
                }
#pragma unroll
                for (int nt = 0; nt < 8; nt++) {
                    const float* p = Bs + kt * 8 * 132 + nt * 8;
                    bf[nt][0] = __float_as_uint(p[0]);
                    bf[nt][1] = __float_as_uint(p[4 * 132]);
                }
#pragma unroll
                for (int mt = 0; mt < 2; mt++)
#pragma unroll
                    for (int nt = 0; nt < 8; nt++) mma8(c[mt][nt], a[mt], bf[nt]);
            }
        }
        __syncthreads();

        // epilogue 2: Z = gelu(C + b2); S += columns
#pragma unroll
        for (int mt = 0; mt < 2; mt++)
#pragma unroll
            for (int nt = 0; nt < 8; nt++) {
                int row = mb + mt * 16 + lr;
                int col = nb + nt * 8 + 2 * lc;
                float bb0 = sm[B2_O + col], bb1 = sm[B2_O + col + 1];
                float z0 = gelu_f(c[mt][nt][0] + bb0);
                float z1 = gelu_f(c[mt][nt][1] + bb1);
                float z2 = gelu_f(c[mt][nt][2] + bb0);
                float z3 = gelu_f(c[mt][nt][3] + bb1);
                sacc[nt * 2]     += z0 + z2;
                sacc[nt * 2 + 1] += z1 + z3;
                *(float2*)&sm[Z_O + row * 132 + col]       = make_float2(tf32f(z0), tf32f(z1));
                *(float2*)&sm[Z_O + (row + 8) * 132 + col] = make_float2(tf32f(z2), tf32f(z3));
            }
        __syncthreads();

        // ======== Gram: G += Z^T @ Z ========
        {
#pragma unroll 4
            for (int kt = 0; kt < 16; kt++) {
                uint32_t a[2][4], bf[8][2];
                const float* At = &sm[Z_O + (kt * 8 + lc) * 132 + mb + lr];
#pragma unroll
                for (int mt = 0; mt < 2; mt++) {
                    const float* p = At + mt * 16;
                    a[mt][0] = __float_as_uint(p[0]);
                    a[mt][1] = __float_as_uint(p[8]);
                    a[mt][2] = __float_as_uint(p[4 * 132]);
                    a[mt][3] = __float_as_uint(p[4 * 132 + 8]);
                }
                const float* Bt = &sm[Z_O + (kt * 8 + lc) * 132 + nb + lr];
#pragma unroll
                for (int nt = 0; nt < 8; nt++) {
                    const float* p = Bt + nt * 8;
                    bf[nt][0] = __float_as_uint(p[0]);
                    bf[nt][1] = __float_as_uint(p[4 * 132]);
                }
#pragma unroll
                for (int mt = 0; mt < 2; mt++)
#pragma unroll
                    for (int nt = 0; nt < 8; nt++) mma8(g[mt][nt], a[mt], bf[nt]);
            }
        }
        __syncthreads();
    }

    // ---- contract G with a_h in-register: v_h[col] = sum_rows a_h[row]*G[row][col] ----
    {
        float ar0[2][2], ar1[2][2];
#pragma unroll
        for (int mt = 0; mt < 2; mt++) {
            int row = mb + mt * 16 + lr;
            ar0[mt][0] = sm[SA0_O + row];     ar0[mt][1] = sm[SA0_O + row + 8];
            ar1[mt][0] = sm[SA1_O + row];     ar1[mt][1] = sm[SA1_O + row + 8];
        }
        float v0[16], v1[16];
#pragma unroll
        for (int nt = 0; nt < 8; nt++)
#pragma unroll
            for (int j = 0; j < 2; j++) {
                float s0 = 0.f, s1 = 0.f;
#pragma unroll
                for (int mt = 0; mt < 2; mt++) {
                    s0 = fmaf(ar0[mt][0], g[mt][nt][j],     s0);
                    s0 = fmaf(ar0[mt][1], g[mt][nt][2 + j], s0);
                    s1 = fmaf(ar1[mt][0], g[mt][nt][j],     s1);
                    s1 = fmaf(ar1[mt][1], g[mt][nt][2 + j], s1);
                }
                v0[nt * 2 + j] = s0; v1[nt * 2 + j] = s1;
            }
#pragma unroll
        for (int i = 0; i < 16; i++) {
            v0[i] += __shfl_down_sync(0xFFFFFFFFu, v0[i], 16);
            v0[i] += __shfl_down_sync(0xFFFFFFFFu, v0[i], 8);
            v0[i] += __shfl_down_sync(0xFFFFFFFFu, v0[i], 4);
            v1[i] += __shfl_down_sync(0xFFFFFFFFu, v1[i], 16);
            v1[i] += __shfl_down_sync(0xFFFFFFFFu, v1[i], 8);
            v1[i] += __shfl_down_sync(0xFFFFFFFFu, v1[i], 4);
        }
        if (lr == 0) {
#pragma unroll
            for (int i = 0; i < 16; i++) {
                int col = nb + (i >> 1) * 8 + 2 * lc + (i & 1);
                atomicAdd(&sm[SV_O + col],       v0[i]);
                atomicAdd(&sm[SV_O + 128 + col], v1[i]);
            }
        }
    }

    // ---- reduce S ----
#pragma unroll
    for (int i = 0; i < 16; i++) {
        float v = sacc[i];
        v += __shfl_down_sync(0xFFFFFFFFu, v, 16);
        v += __shfl_down_sync(0xFFFFFFFFu, v, 8);
        v += __shfl_down_sync(0xFFFFFFFFu, v, 4);
        if (lr == 0) atomicAdd(&sm[SS_O + nb + (i >> 1) * 8 + 2 * lc + (i & 1)], v);
    }
    __syncthreads();
    if (tid < 128) g_partS[bid][tid] = sm[SS_O + tid];
    g_partV[bid][tid] = sm[SV_O + tid];
}

// ================= tail: two fully-unrolled load phases =================
__global__ void tail_kernel(const float* __restrict__ Wv, const float* __restrict__ bv,
                            const float* __restrict__ Wo, const float* __restrict__ bo,
                            float* __restrict__ out)
{
    __shared__ float ss[DD], w0[DD], w1[DD], sa0[DD], sa1[DD], sattn[DD];
    const int t = threadIdx.x;   // 0..127
    const int b = blockIdx.x;    // 0..31

    float s  = g_partS[b*4][t] + g_partS[b*4+1][t] + g_partS[b*4+2][t] + g_partS[b*4+3][t];
    float v0 = g_partV[b*4][t] + g_partV[b*4+1][t] + g_partV[b*4+2][t] + g_partV[b*4+3][t];
    float v1 = g_partV[b*4][128+t] + g_partV[b*4+1][128+t] + g_partV[b*4+2][128+t] + g_partV[b*4+3][128+t];
    const float qbk0 = g_qbk[0], qbk1 = g_qbk[1];

    ss[t]  = s;
    w0[t]  = v0 + qbk0 * s;
    w1[t]  = v1 + qbk1 * s;
    sa0[t] = g_a0[t];
    sa1[t] = g_a1[t];
    __syncthreads();

    // asd_h = a_h . s  (redundant per-thread, smem broadcast; full unroll)
    float asd0 = 0.f, asd1 = 0.f;
#pragma unroll
    for (int q = 0; q < DD; q++) {
        asd0 = fmaf(sa0[q], ss[q], asd0);
        asd1 = fmaf(sa1[q], ss[q], asd1);
    }

    // y[t] = sum_q w_{h(t)}[q] * Wv[q][t]  (full unroll -> all loads in flight)
    const int h = t >> 6;
    const float* wh = h ? w1 : w0;
    float y = 0.f;
#pragma unroll
    for (int q = 0; q < DD; q++) y = fmaf(wh[q], Wv[q * DD + t], y);

    float asd = h ? asd1 : asd0;
    float qbk = h ? qbk1 : qbk0;
    sattn[t] = (y + (asd + (float)NN * qbk) * bv[t]) * (1.0f / (float)NN);
    __syncthreads();

    // out = attn @ Wo + bo  (full unroll)
    float o = bo[t];
#pragma unroll
    for (int i = 0; i < DD; i++) o = fmaf(sattn[i], Wo[i * DD + t], o);
    out[b * DD + t] = o;
}

// ================= launch =================
extern "C" void kernel_launch(void* const* d_in, const int* in_sizes, int n_in,
                              void* d_out, int out_size)
{
    const float* u     = (const float*)d_in[0];
    const float* W1    = (const float*)d_in[2];
    const float* b1    = (const float*)d_in[3];
    const float* W2    = (const float*)d_in[4];
    const float* b2    = (const float*)d_in[5];
    const float* embed = (const float*)d_in[6];
    const float* Wq    = (const float*)d_in[7];
    const float* bq    = (const float*)d_in[8];
    const float* Wk    = (const float*)d_in[9];
    const float* bk    = (const float*)d_in[10];
    const float* Wv    = (const float*)d_in[11];
    const float* bv    = (const float*)d_in[12];
    const float* Wo    = (const float*)d_in[13];
    const float* bo    = (const float*)d_in[14];
    float* out = (float*)d_out;

    cudaFuncSetAttribute(fused_mma_kernel,
                         cudaFuncAttributeMaxDynamicSharedMemorySize, SMEM_BYTES);

    fused_mma_kernel<<<NBLK, 256, SMEM_BYTES>>>(u, W1, b1, W2, b2, embed, Wq, bq, Wk, bk);
    tail_kernel<<<BB, DD>>>(Wv, bv, Wo, bo, out);
}

// round 11
// speedup vs baseline: 1.8355x; 1.0936x over previous
#include <cuda_runtime.h>
#include <cstdint>

#define BB 32
#define NN 4096
#define DU 64
#define DD 128
#define TILES 8
#define CHUNKS 4
#define NBLK (BB*CHUNKS)     // 128 blocks, single wave

// shared-memory layout (float offsets)
#define W1_O 0                       // [64][132]
#define W2_O (W1_O + 64*132)         // [128][132]
#define U_O  (W2_O + 128*132)        // [128][68]
#define Z_O  (U_O  + 128*68)         // [128][132] (Z1/Z aliased; Wk staging post-loop, pitch 129)
#define B1_O (Z_O  + 128*132)
#define B2_O (B1_O + 128)
#define SQF_O (B2_O + 128)
#define SA0_O (SQF_O + 128)
#define SA1_O (SA0_O + 128)
#define SLOTV_O (SA1_O + 128)       // [4][256]
#define SLOTS_O (SLOTV_O + 1024)    // [4][128]
#define SMEM_FLOATS (SLOTS_O + 512)
#define SMEM_BYTES (SMEM_FLOATS * 4) // ~214 KB

__device__ float g_partV[NBLK][256];   // per-block a^T G partials (2 heads x 128)
__device__ float g_partS[NBLK][DD];
__device__ float g_a0[DD], g_a1[DD];   // a_h = Wk^T qf (written by block 0)
__device__ float g_qbk[2];             // qf_h . bk_h  (written by block 0)

static __device__ __forceinline__ uint32_t tf32r(float f) {
    uint32_t r; asm("cvt.rna.tf32.f32 %0, %1;" : "=r"(r) : "f"(f)); return r;
}
static __device__ __forceinline__ float tf32f(float f) {
    return __uint_as_float(tf32r(f));
}
// jax.nn.gelu approximate
static __device__ __forceinline__ float gelu_f(float x) {
    float x2 = x * x;
    float y2 = x * fmaf(0.0713548162f, x2, 1.5957691216f);
    float e  = __expf(y2);
    return x - __fdividef(x, e + 1.0f);
}
// m16n8k8 tf32 HMMA, D = A*B + D
static __device__ __forceinline__ void mma8(float* c, const uint32_t* a, const uint32_t* b) {
    asm volatile(
        "mma.sync.aligned.m16n8k8.row.col.f32.tf32.tf32.f32 "
        "{%0,%1,%2,%3},{%4,%5,%6,%7},{%8,%9},{%0,%1,%2,%3};"
        : "+f"(c[0]), "+f"(c[1]), "+f"(c[2]), "+f"(c[3])
        : "r"(a[0]), "r"(a[1]), "r"(a[2]), "r"(a[3]), "r"(b[0]), "r"(b[1]));
}

// ================= main fused kernel =================
__global__ void __launch_bounds__(256, 1)
fused_mma_kernel(const float* __restrict__ u,
                 const float* __restrict__ W1, const float* __restrict__ b1,
                 const float* __restrict__ W2, const float* __restrict__ b2,
                 const float* __restrict__ embed,
                 const float* __restrict__ Wq, const float* __restrict__ bq,
                 const float* __restrict__ Wk, const float* __restrict__ bk)
{
    extern __shared__ float sm[];
    const int tid  = threadIdx.x;
    const int w    = tid >> 5;
    const int lane = tid & 31;
    const int lr   = lane >> 2;      // fragment row group 0..7
    const int lc   = lane & 3;       // fragment k group 0..3
    const int mb   = (w >> 1) * 32;  // warp row base
    const int nb   = (w & 1) * 64;   // warp col base
    const int bid  = blockIdx.x;

    // ---- stage weights as tf32 ----
    for (int i = tid; i < 64 * 128; i += 256) {
        int k = i >> 7, n = i & 127;
        sm[W1_O + k * 132 + n] = tf32f(W1[i]);
    }
    for (int i = tid; i < 128 * 128; i += 256) {
        int k = i >> 7, n = i & 127;
        sm[W2_O + k * 132 + n] = tf32f(W2[i]);
    }
    if (tid < 128) {
        sm[B1_O + tid] = b1[tid]; sm[B2_O + tid] = b2[tid];
        // qf[t] = embed @ Wq + bq  (coalesced: consecutive t -> consecutive addr)
        float acc = bq[tid];
#pragma unroll 8
        for (int p = 0; p < DD; p++) acc = fmaf(embed[p], Wq[p * DD + tid], acc);
        sm[SQF_O + tid] = acc;
    }

    float g[2][8][4];     // Gram accumulators
#pragma unroll
    for (int mt = 0; mt < 2; mt++)
#pragma unroll
        for (int nt = 0; nt < 8; nt++)
#pragma unroll
            for (int i = 0; i < 4; i++) g[mt][nt][i] = 0.f;
    float sacc[16];
#pragma unroll
    for (int i = 0; i < 16; i++) sacc[i] = 0.f;

    const float* ub = u + ((size_t)(bid >> 2) * NN + (size_t)(bid & 3) * 1024) * DU;

    __syncthreads();

    // per-thread bias copies (R6-proven)
    float b1r[16], b2r[16];
#pragma unroll
    for (int nt = 0; nt < 8; nt++) {
        int col = nb + nt * 8 + 2 * lc;
        b1r[nt * 2] = sm[B1_O + col]; b1r[nt * 2 + 1] = sm[B1_O + col + 1];
        b2r[nt * 2] = sm[B2_O + col]; b2r[nt * 2 + 1] = sm[B2_O + col + 1];
    }

    // prefetch tile 0 into registers (R6-proven)
    float4 pref[8];
    {
        const float4* uv = (const float4*)ub;
#pragma unroll
        for (int i = 0; i < 8; i++) pref[i] = uv[i * 256 + tid];
    }

    for (int tt = 0; tt < TILES; tt++) {
        // ---- store prefetched U tile (tf32, pitch 68), then prefetch next ----
#pragma unroll
        for (int i = 0; i < 8; i++) {
            int idx = i * 256 + tid;
            int tok = idx >> 4, kq = idx & 15;
            float4 f = pref[i];
            *(float4*)&sm[U_O + tok * 68 + kq * 4] =
                make_float4(tf32f(f.x), tf32f(f.y), tf32f(f.z), tf32f(f.w));
        }
        if (tt + 1 < TILES) {
            const float4* uv = (const float4*)(ub + (size_t)(tt + 1) * 128 * DU);
#pragma unroll
            for (int i = 0; i < 8; i++) pref[i] = uv[i * 256 + tid];
        }
        __syncthreads();

        float c[2][8][4];

        // ======== MLP1: C = U @ W1  (K=64) ========
#pragma unroll
        for (int mt = 0; mt < 2; mt++)
#pragma unroll
            for (int nt = 0; nt < 8; nt++)
#pragma unroll
                for (int i = 0; i < 4; i++) c[mt][nt][i] = 0.f;
        {
            const float* As = &sm[U_O + (mb + lr) * 68 + lc];
            const float* Bs = &sm[W1_O + lc * 132 + nb + lr];
#pragma unroll 4
            for (int kt = 0; kt < 8; kt++) {
                uint32_t a[2][4], bf[8][2];
#pragma unroll
                for (int mt = 0; mt < 2; mt++) {
                    const float* p = As + mt * 16 * 68 + kt * 8;
                    a[mt][0] = __float_as_uint(p[0]);
                    a[mt][1] = __float_as_uint(p[8 * 68]);
                    a[mt][2] = __float_as_uint(p[4]);
                    a[mt][3] = __float_as_uint(p[8 * 68 + 4]);
                }
#pragma unroll
                for (int nt = 0; nt < 8; nt++) {
                    const float* p = Bs + kt * 8 * 132 + nt * 8;
                    bf[nt][0] = __float_as_uint(p[0]);
                    bf[nt][1] = __float_as_uint(p[4 * 132]);
                }
#pragma unroll
                for (int mt = 0; mt < 2; mt++)
#pragma unroll
                    for (int nt = 0; nt < 8; nt++) mma8(c[mt][nt], a[mt], bf[nt]);
            }
        }
        __syncthreads();

        // epilogue 1: Z1 = gelu(C + b1)
#pragma unroll
        for (int mt = 0; mt < 2; mt++)
#pragma unroll
            for (int nt = 0; nt < 8; nt++) {
                int row = mb + mt * 16 + lr;
                int col = nb + nt * 8 + 2 * lc;
                float z0 = gelu_f(c[mt][nt][0] + b1r[nt * 2]);
                float z1 = gelu_f(c[mt][nt][1] + b1r[nt * 2 + 1]);
                float z2 = gelu_f(c[mt][nt][2] + b1r[nt * 2]);
                float z3 = gelu_f(c[mt][nt][3] + b1r[nt * 2 + 1]);
                *(float2*)&sm[Z_O + row * 132 + col]       = make_float2(tf32f(z0), tf32f(z1));
                *(float2*)&sm[Z_O + (row + 8) * 132 + col] = make_float2(tf32f(z2), tf32f(z3));
            }
        __syncthreads();

        // ======== MLP2: C = Z1 @ W2  (K=128) ========
#pragma unroll
        for (int mt = 0; mt < 2; mt++)
#pragma unroll
            for (int nt = 0; nt < 8; nt++)
#pragma unroll
                for (int i = 0; i < 4; i++) c[mt][nt][i] = 0.f;
        {
            const float* As = &sm[Z_O + (mb + lr) * 132 + lc];
            const float* Bs = &sm[W2_O + lc * 132 + nb + lr];
#pragma unroll 4
            for (int kt = 0; kt < 16; kt++) {
                uint32_t a[2][4], bf[8][2];
#pragma unroll
                for (int mt = 0; mt < 2; mt++) {
                    const float* p = As + mt * 16 * 132 + kt * 8;
                    a[mt][0] = __float_as_uint(p[0]);
                    a[mt][1] = __float_as_uint(p[8 * 132]);
                    a[mt][2] = __float_as_uint(p[4]);
                    a[mt][3] = __float_as_uint(p[8 * 132 + 4]);
                }
#pragma unroll
                for (int nt = 0; nt < 8; nt++) {
                    const float* p = Bs + kt * 8 * 132 + nt * 8;
                    bf[nt][0] = __float_as_uint(p[0]);
                    bf[nt][1] = __float_as_uint(p[4 * 132]);
                }
#pragma unroll
                for (int mt = 0; mt < 2; mt++)
#pragma unroll
                    for (int nt = 0; nt < 8; nt++) mma8(c[mt][nt], a[mt], bf[nt]);
            }
        }
        __syncthreads();

        // epilogue 2: Z = gelu(C + b2); S += columns
#pragma unroll
        for (int mt = 0; mt < 2; mt++)
#pragma unroll
            for (int nt = 0; nt < 8; nt++) {
                int row = mb + mt * 16 + lr;
                int col = nb + nt * 8 + 2 * lc;
                float z0 = gelu_f(c[mt][nt][0] + b2r[nt * 2]);
                float z1 = gelu_f(c[mt][nt][1] + b2r[nt * 2 + 1]);
                float z2 = gelu_f(c[mt][nt][2] + b2r[nt * 2]);
                float z3 = gelu_f(c[mt][nt][3] + b2r[nt * 2 + 1]);
                sacc[nt * 2]     += z0 + z2;
                sacc[nt * 2 + 1] += z1 + z3;
                *(float2*)&sm[Z_O + row * 132 + col]       = make_float2(tf32f(z0), tf32f(z1));
                *(float2*)&sm[Z_O + (row + 8) * 132 + col] = make_float2(tf32f(z2), tf32f(z3));
            }
        __syncthreads();

        // ======== Gram: G += Z^T @ Z ========
        {
#pragma unroll 4
            for (int kt = 0; kt < 16; kt++) {
                uint32_t a[2][4], bf[8][2];
                const float* At = &sm[Z_O + (kt * 8 + lc) * 132 + mb + lr];
#pragma unroll
                for (int mt = 0; mt < 2; mt++) {
                    const float* p = At + mt * 16;
                    a[mt][0] = __float_as_uint(p[0]);
                    a[mt][1] = __float_as_uint(p[8]);
                    a[mt][2] = __float_as_uint(p[4 * 132]);
                    a[mt][3] = __float_as_uint(p[4 * 132 + 8]);
                }
                const float* Bt = &sm[Z_O + (kt * 8 + lc) * 132 + nb + lr];
#pragma unroll
                for (int nt = 0; nt < 8; nt++) {
                    const float* p = Bt + nt * 8;
                    bf[nt][0] = __float_as_uint(p[0]);
                    bf[nt][1] = __float_as_uint(p[4 * 132]);
                }
#pragma unroll
                for (int mt = 0; mt < 2; mt++)
#pragma unroll
                    for (int nt = 0; nt < 8; nt++) mma8(g[mt][nt], a[mt], bf[nt]);
            }
        }
        __syncthreads();
    }

    // ================= post-loop =================
    // stage Wk into the now-dead Z region, coalesced, pitch 129 (conflict-free column reads)
    for (int i = tid; i < 128 * 128; i += 256) {
        int r = i >> 7, d = i & 127;
        sm[Z_O + r * 129 + d] = Wk[i];
    }
    __syncthreads();

    // a_h[p] = sum_d qf[h*64+d] * Wk[p][h*64+d]   (all smem, conflict-free)
    if (tid < 128) {
        float a0 = 0.f, a1 = 0.f;
        const float* wkr = &sm[Z_O + tid * 129];
#pragma unroll 16
        for (int d = 0; d < 64; d++) {
            a0 = fmaf(sm[SQF_O + d],      wkr[d],      a0);
            a1 = fmaf(sm[SQF_O + 64 + d], wkr[64 + d], a1);
        }
        sm[SA0_O + tid] = a0; sm[SA1_O + tid] = a1;
        if (bid == 0) {
            g_a0[tid] = a0; g_a1[tid] = a1;
            if (tid < 2) {
                float s = 0.f;
#pragma unroll 16
                for (int d = 0; d < 64; d++)
                    s = fmaf(sm[SQF_O + tid * 64 + d], bk[tid * 64 + d], s);
                g_qbk[tid] = s;
            }
        }
    }
    __syncthreads();

    // contract G with a_h: per-warp slots (no atomics)
    {
        float ar00 = sm[SA0_O + mb + lr],      ar01 = sm[SA0_O + mb + lr + 8];
        float ar02 = sm[SA0_O + mb + 16 + lr], ar03 = sm[SA0_O + mb + 16 + lr + 8];
        float ar10 = sm[SA1_O + mb + lr],      ar11 = sm[SA1_O + mb + lr + 8];
        float ar12 = sm[SA1_O + mb + 16 + lr], ar13 = sm[SA1_O + mb + 16 + lr + 8];
        float* slot = &sm[SLOTV_O + (w >> 1) * 256];
#pragma unroll
        for (int nt = 0; nt < 8; nt++) {
#pragma unroll
            for (int j = 0; j < 2; j++) {
                float s0 = ar00 * g[0][nt][j] + ar01 * g[0][nt][2 + j]
                         + ar02 * g[1][nt][j] + ar03 * g[1][nt][2 + j];
                float s1 = ar10 * g[0][nt][j] + ar11 * g[0][nt][2 + j]
                         + ar12 * g[1][nt][j] + ar13 * g[1][nt][2 + j];
                s0 += __shfl_down_sync(0xFFFFFFFFu, s0, 16);
                s0 += __shfl_down_sync(0xFFFFFFFFu, s0, 8);
                s0 += __shfl_down_sync(0xFFFFFFFFu, s0, 4);
                s1 += __shfl_down_sync(0xFFFFFFFFu, s1, 16);
                s1 += __shfl_down_sync(0xFFFFFFFFu, s1, 8);
                s1 += __shfl_down_sync(0xFFFFFFFFu, s1, 4);
                if (lr == 0) {
                    int col = nb + nt * 8 + 2 * lc + j;
                    slot[col]       = s0;
                    slot[128 + col] = s1;
                }
            }
        }
        // S columns: same slot scheme
        float* slotS = &sm[SLOTS_O + (w >> 1) * 128];
#pragma unroll
        for (int i = 0; i < 16; i++) {
            float v = sacc[i];
            v += __shfl_down_sync(0xFFFFFFFFu, v, 16);
            v += __shfl_down_sync(0xFFFFFFFFu, v, 8);
            v += __shfl_down_sync(0xFFFFFFFFu, v, 4);
            if (lr == 0) slotS[nb + (i >> 1) * 8 + 2 * lc + (i & 1)] = v;
        }
    }
    __syncthreads();

    // final slot reduce -> global partials
    if (tid < 256) {
        float sv = sm[SLOTV_O + tid] + sm[SLOTV_O + 256 + tid]
                 + sm[SLOTV_O + 512 + tid] + sm[SLOTV_O + 768 + tid];
        g_partV[bid][tid] = sv;
    }
    if (tid < 128) {
        float s = sm[SLOTS_O + tid] + sm[SLOTS_O + 128 + tid]
                + sm[SLOTS_O + 256 + tid] + sm[SLOTS_O + 384 + tid];
        g_partS[bid][tid] = s;
    }
}

// ================= tail: 4-way k-split, 512 threads =================
__global__ void tail_kernel(const float* __restrict__ Wv, const float* __restrict__ bv,
                            const float* __restrict__ Wo, const float* __restrict__ bo,
                            float* __restrict__ out)
{
    __shared__ float r3[4][3][DD];
    __shared__ float ss[DD], w0[DD], w1[DD], sa0[DD], sa1[DD], sattn[DD];
    const int t    = threadIdx.x & 127;
    const int part = threadIdx.x >> 7;   // 0..3
    const int b    = blockIdx.x;
    const float qbk0 = g_qbk[0], qbk1 = g_qbk[1];

    // phase 0: partial loads (4-way) + stage a vectors
    r3[part][0][t] = g_partS[b * 4 + part][t];
    r3[part][1][t] = g_partV[b * 4 + part][t];
    r3[part][2][t] = g_partV[b * 4 + part][128 + t];
    if (part == 1) sa0[t] = g_a0[t];
    if (part == 2) sa1[t] = g_a1[t];
    __syncthreads();

    if (part == 0) {
        float S  = r3[0][0][t] + r3[1][0][t] + r3[2][0][t] + r3[3][0][t];
        float V0 = r3[0][1][t] + r3[1][1][t] + r3[2][1][t] + r3[3][1][t];
        float V1 = r3[0][2][t] + r3[1][2][t] + r3[2][2][t] + r3[3][2][t];
        ss[t] = S;
        w0[t] = V0 + qbk0 * S;
        w1[t] = V1 + qbk1 * S;
    }
    __syncthreads();

    // asd_h = a_h . s  (redundant per-thread; smem broadcast)
    float asd0 = 0.f, asd1 = 0.f;
#pragma unroll
    for (int q = 0; q < DD; q++) {
        asd0 = fmaf(sa0[q], ss[q], asd0);
        asd1 = fmaf(sa1[q], ss[q], asd1);
    }

    // y[t] = sum_q w_h[q] * Wv[q][t]  — 4-way split over q
    const int h = t >> 6;
    const float* wh = h ? w1 : w0;
    {
        float yp = 0.f;
        const int q0 = part * 32;
#pragma unroll
        for (int qq = 0; qq < 32; qq++)
            yp = fmaf(wh[q0 + qq], Wv[(q0 + qq) * DD + t], yp);
        r3[part][0][t] = yp;
    }
    __syncthreads();

    if (part == 0) {
        float y = r3[0][0][t] + r3[1][0][t] + r3[2][0][t] + r3[3][0][t];
        float asd = h ? asd1 : asd0;
        float qbk = h ? qbk1 : qbk0;
        sattn[t] = (y + (asd + (float)NN * qbk) * bv[t]) * (1.0f / (float)NN);
    }
    __syncthreads();

    // out = attn @ Wo + bo — 4-way split over i
    {
        float op = 0.f;
        const int i0 = part * 32;
#pragma unroll
        for (int ii = 0; ii < 32; ii++)
            op = fmaf(sattn[i0 + ii], Wo[(i0 + ii) * DD + t], op);
        r3[part][1][t] = op;
    }
    __syncthreads();

    if (part == 0)
        out[b * DD + t] = bo[t] + r3[0][1][t] + r3[1][1][t] + r3[2][1][t] + r3[3][1][t];
}

// ================= launch =================
extern "C" void kernel_launch(void* const* d_in, const int* in_sizes, int n_in,
                              void* d_out, int out_size)
{
    const float* u     = (const float*)d_in[0];
    const float* W1    = (const float*)d_in[2];
    const float* b1    = (const float*)d_in[3];
    const float* W2    = (const float*)d_in[4];
    const float* b2    = (const float*)d_in[5];
    const float* embed = (const float*)d_in[6];
    const float* Wq    = (const float*)d_in[7];
    const float* bq    = (const float*)d_in[8];
    const float* Wk    = (const float*)d_in[9];
    const float* bk    = (const float*)d_in[10];
    const float* Wv    = (const float*)d_in[11];
    const float* bv    = (const float*)d_in[12];
    const float* Wo    = (const float*)d_in[13];
    const float* bo    = (const float*)d_in[14];
    float* out = (float*)d_out;

    cudaFuncSetAttribute(fused_mma_kernel,
                         cudaFuncAttributeMaxDynamicSharedMemorySize, SMEM_BYTES);

    fused_mma_kernel<<<NBLK, 256, SMEM_BYTES>>>(u, W1, b1, W2, b2, embed, Wq, bq, Wk, bk);
    tail_kernel<<<BB, 512>>>(Wv, bv, Wo, bo, out);
}

// round 14
// speedup vs baseline: 1.8647x; 1.0159x over previous
#include <cuda_runtime.h>
#include <cstdint>

#define BB 32
#define NN 4096
#define DU 64
#define DD 128
#define TILES 8
#define CHUNKS 4
#define NBLK (BB*CHUNKS)     // 128 blocks, single wave

// shared-memory layout (float offsets)
#define W1_O 0                       // [64][132]
#define W2_O (W1_O + 64*132)         // [128][132]
#define U_O  (W2_O + 128*132)        // [128][68]
#define Z_O  (U_O  + 128*68)         // [128][132] (Z1/Z aliased; Wk staging post-loop, pitch 129)
#define B1_O (Z_O  + 128*132)
#define B2_O (B1_O + 128)
#define SQF_O (B2_O + 128)
#define SA0_O (SQF_O + 128)
#define SA1_O (SA0_O + 128)
#define SLOTV_O (SA1_O + 128)       // [4][256]
#define SLOTS_O (SLOTV_O + 1024)    // [4][128]  (also qf half-1 partial at start)
#define SMEM_FLOATS (SLOTS_O + 512)
#define SMEM_BYTES (SMEM_FLOATS * 4) // ~214 KB

__device__ float g_partV[NBLK][256];   // per-block a^T G partials (2 heads x 128)
__device__ float g_partS[NBLK][DD];
__device__ float g_a0[DD], g_a1[DD];   // a_h = Wk^T qf (written by block 0)
__device__ float g_qbk[2];             // qf_h . bk_h  (written by block 0)

static __device__ __forceinline__ uint32_t tf32r(float f) {
    uint32_t r; asm("cvt.rna.tf32.f32 %0, %1;" : "=r"(r) : "f"(f)); return r;
}
static __device__ __forceinline__ float tf32f(float f) {
    return __uint_as_float(tf32r(f));
}
// jax.nn.gelu approximate
static __device__ __forceinline__ float gelu_f(float x) {
    float x2 = x * x;
    float y2 = x * fmaf(0.0713548162f, x2, 1.5957691216f);
    float e  = __expf(y2);
    return x - __fdividef(x, e + 1.0f);
}
// m16n8k8 tf32 HMMA, D = A*B + D
static __device__ __forceinline__ void mma8(float* c, const uint32_t* a, const uint32_t* b) {
    asm volatile(
        "mma.sync.aligned.m16n8k8.row.col.f32.tf32.tf32.f32 "
        "{%0,%1,%2,%3},{%4,%5,%6,%7},{%8,%9},{%0,%1,%2,%3};"
        : "+f"(c[0]), "+f"(c[1]), "+f"(c[2]), "+f"(c[3])
        : "r"(a[0]), "r"(a[1]), "r"(a[2]), "r"(a[3]), "r"(b[0]), "r"(b[1]));
}

// ================= main fused kernel =================
__global__ void __launch_bounds__(256, 1)
fused_mma_kernel(const float* __restrict__ u,
                 const float* __restrict__ W1, const float* __restrict__ b1,
                 const float* __restrict__ W2, const float* __restrict__ b2,
                 const float* __restrict__ embed,
                 const float* __restrict__ Wq, const float* __restrict__ bq,
                 const float* __restrict__ Wk, const float* __restrict__ bk)
{
    extern __shared__ float sm[];
    const int tid  = threadIdx.x;
    const int w    = tid >> 5;
    const int lane = tid & 31;
    const int lr   = lane >> 2;      // fragment row group 0..7
    const int lc   = lane & 3;       // fragment k group 0..3
    const int mb   = (w >> 1) * 32;  // warp row base
    const int nb   = (w & 1) * 64;   // warp col base
    const int bid  = blockIdx.x;

    // ---- stage weights as tf32 ----
    for (int i = tid; i < 64 * 128; i += 256) {
        int k = i >> 7, n = i & 127;
        sm[W1_O + k * 132 + n] = tf32f(W1[i]);
    }
    for (int i = tid; i < 128 * 128; i += 256) {
        int k = i >> 7, n = i & 127;
        sm[W2_O + k * 132 + n] = tf32f(W2[i]);
    }
    if (tid < 128) {
        sm[B1_O + tid] = b1[tid]; sm[B2_O + tid] = b2[tid];
    }
    // qf partial: all 256 threads, 2-way split over p
    {
        const int t = tid & 127, half = tid >> 7;
        const float* wq = Wq + (size_t)(half * 64) * DD + t;
        const float* eb = embed + half * 64;
        float acc = 0.f;
#pragma unroll 8
        for (int p = 0; p < 64; p++) acc = fmaf(eb[p], wq[(size_t)p * DD], acc);
        sm[(half ? SLOTS_O : SQF_O) + t] = acc;
    }

    float g[2][8][4];     // Gram accumulators
#pragma unroll
    for (int mt = 0; mt < 2; mt++)
#pragma unroll
        for (int nt = 0; nt < 8; nt++)
#pragma unroll
            for (int i = 0; i < 4; i++) g[mt][nt][i] = 0.f;
    float sacc[16];
#pragma unroll
    for (int i = 0; i < 16; i++) sacc[i] = 0.f;

    const float* ub = u + ((size_t)(bid >> 2) * NN + (size_t)(bid & 3) * 1024) * DU;

    __syncthreads();

    // combine qf halves (value needed only post-loop; later syncs cover visibility)
    if (tid < 128)
        sm[SQF_O + tid] = sm[SQF_O + tid] + sm[SLOTS_O + tid] + bq[tid];

    // per-thread bias copies
    float b1r[16], b2r[16];
#pragma unroll
    for (int nt = 0; nt < 8; nt++) {
        int col = nb + nt * 8 + 2 * lc;
        b1r[nt * 2] = sm[B1_O + col]; b1r[nt * 2 + 1] = sm[B1_O + col + 1];
        b2r[nt * 2] = sm[B2_O + col]; b2r[nt * 2 + 1] = sm[B2_O + col + 1];
    }

    for (int tt = 0; tt < TILES; tt++) {
        // ---- load U tile (128 tok x 64) direct to smem as tf32, pitch 68 ----
        {
            const float4* uv = (const float4*)(ub + (size_t)tt * 128 * DU);
#pragma unroll
            for (int i = 0; i < 8; i++) {
                int idx = i * 256 + tid;
                int tok = idx >> 4, kq = idx & 15;
                float4 f = uv[idx];
                *(float4*)&sm[U_O + tok * 68 + kq * 4] =
                    make_float4(tf32f(f.x), tf32f(f.y), tf32f(f.z), tf32f(f.w));
            }
        }
        __syncthreads();

        float c[2][8][4];

        // ======== MLP1: C = U @ W1  (K=64) ========
#pragma unroll
        for (int mt = 0; mt < 2; mt++)
#pragma unroll
            for (int nt = 0; nt < 8; nt++)
#pragma unroll
                for (int i = 0; i < 4; i++) c[mt][nt][i] = 0.f;
        {
            const float* As = &sm[U_O + (mb + lr) * 68 + lc];
            const float* Bs = &sm[W1_O + lc * 132 + nb + lr];
#pragma unroll 4
            for (int kt = 0; kt < 8; kt++) {
                uint32_t a[2][4], bf[8][2];
#pragma unroll
                for (int mt = 0; mt < 2; mt++) {
                    const float* p = As + mt * 16 * 68 + kt * 8;
                    a[mt][0] = __float_as_uint(p[0]);
                    a[mt][1] = __float_as_uint(p[8 * 68]);
                    a[mt][2] = __float_as_uint(p[4]);
                    a[mt][3] = __float_as_uint(p[8 * 68 + 4]);
                }
#pragma unroll
                for (int nt = 0; nt < 8; nt++) {
                    const float* p = Bs + kt * 8 * 132 + nt * 8;
                    bf[nt][0] = __float_as_uint(p[0]);
                    bf[nt][1] = __float_as_uint(p[4 * 132]);
                }
#pragma unroll
                for (int mt = 0; mt < 2; mt++)
#pragma unroll
                    for (int nt = 0; nt < 8; nt++) mma8(c[mt][nt], a[mt], bf[nt]);
            }
        }
        __syncthreads();

        // epilogue 1: Z1 = gelu(C + b1)
#pragma unroll
        for (int mt = 0; mt < 2; mt++)
#pragma unroll
            for (int nt = 0; nt < 8; nt++) {
                int row = mb + mt * 16 + lr;
                int col = nb + nt * 8 + 2 * lc;
                float z0 = gelu_f(c[mt][nt][0] + b1r[nt * 2]);
                float z1 = gelu_f(c[mt][nt][1] + b1r[nt * 2 + 1]);
                float z2 = gelu_f(c[mt][nt][2] + b1r[nt * 2]);
                float z3 = gelu_f(c[mt][nt][3] + b1r[nt * 2 + 1]);
                *(float2*)&sm[Z_O + row * 132 + col]       = make_float2(tf32f(z0), tf32f(z1));
                *(float2*)&sm[Z_O + (row + 8) * 132 + col] = make_float2(tf32f(z2), tf32f(z3));
            }
        __syncthreads();

        // ======== MLP2: C = Z1 @ W2  (K=128) ========
#pragma unroll
        for (int mt = 0; mt < 2; mt++)
#pragma unroll
            for (int nt = 0; nt < 8; nt++)
#pragma unroll
                for (int i = 0; i < 4; i++) c[mt][nt][i] = 0.f;
        {
            const float* As = &sm[Z_O + (mb + lr) * 132 + lc];
            const float* Bs = &sm[W2_O + lc * 132 + nb + lr];
#pragma unroll 4
            for (int kt = 0; kt < 16; kt++) {
                uint32_t a[2][4], bf[8][2];
#pragma unroll
                for (int mt = 0; mt < 2; mt++) {
                    const float* p = As + mt * 16 * 132 + kt * 8;
                    a[mt][0] = __float_as_uint(p[0]);
                    a[mt][1] = __float_as_uint(p[8 * 132]);
                    a[mt][2] = __float_as_uint(p[4]);
                    a[mt][3] = __float_as_uint(p[8 * 132 + 4]);
                }
#pragma unroll
                for (int nt = 0; nt < 8; nt++) {
                    const float* p = Bs + kt * 8 * 132 + nt * 8;
                    bf[nt][0] = __float_as_uint(p[0]);
                    bf[nt][1] = __float_as_uint(p[4 * 132]);
                }
#pragma unroll
                for (int mt = 0; mt < 2; mt++)
#pragma unroll
                    for (int nt = 0; nt < 8; nt++) mma8(c[mt][nt], a[mt], bf[nt]);
            }
        }
        __syncthreads();

        // epilogue 2: Z = gelu(C + b2); S += columns
#pragma unroll
        for (int mt = 0; mt < 2; mt++)
#pragma unroll
            for (int nt = 0; nt < 8; nt++) {
                int row = mb + mt * 16 + lr;
                int col = nb + nt * 8 + 2 * lc;
                float z0 = gelu_f(c[mt][nt][0] + b2r[nt * 2]);
                float z1 = gelu_f(c[mt][nt][1] + b2r[nt * 2 + 1]);
                float z2 = gelu_f(c[mt][nt][2] + b2r[nt * 2]);
                float z3 = gelu_f(c[mt][nt][3] + b2r[nt * 2 + 1]);
                sacc[nt * 2]     += z0 + z2;
                sacc[nt * 2 + 1] += z1 + z3;
                *(float2*)&sm[Z_O + row * 132 + col]       = make_float2(tf32f(z0), tf32f(z1));
                *(float2*)&sm[Z_O + (row + 8) * 132 + col] = make_float2(tf32f(z2), tf32f(z3));
            }
        __syncthreads();

        // ======== Gram: G += Z^T @ Z ========
        {
#pragma unroll 4
            for (int kt = 0; kt < 16; kt++) {
                uint32_t a[2][4], bf[8][2];
                const float* At = &sm[Z_O + (kt * 8 + lc) * 132 + mb + lr];
#pragma unroll
                for (int mt = 0; mt < 2; mt++) {
                    const float* p = At + mt * 16;
                    a[mt][0] = __float_as_uint(p[0]);
                    a[mt][1] = __float_as_uint(p[8]);
                    a[mt][2] = __float_as_uint(p[4 * 132]);
                    a[mt][3] = __float_as_uint(p[4 * 132 + 8]);
                }
                const float* Bt = &sm[Z_O + (kt * 8 + lc) * 132 + nb + lr];
#pragma unroll
                for (int nt = 0; nt < 8; nt++) {
                    const float* p = Bt + nt * 8;
                    bf[nt][0] = __float_as_uint(p[0]);
                    bf[nt][1] = __float_as_uint(p[4 * 132]);
                }
#pragma unroll
                for (int mt = 0; mt < 2; mt++)
#pragma unroll
                    for (int nt = 0; nt < 8; nt++) mma8(g[mt][nt], a[mt], bf[nt]);
            }
        }
        __syncthreads();
    }

    // ================= post-loop =================
    // stage Wk into the now-dead Z region, coalesced, pitch 129 (conflict-free column reads)
    for (int i = tid; i < 128 * 128; i += 256) {
        int r = i >> 7, d = i & 127;
        sm[Z_O + r * 129 + d] = Wk[i];
    }
    __syncthreads();

    // a_h[p] = sum_d qf[h*64+d] * Wk[p][h*64+d]   (all smem, conflict-free)
    if (tid < 128) {
        float a0 = 0.f, a1 = 0.f;
        const float* wkr = &sm[Z_O + tid * 129];
#pragma unroll 16
        for (int d = 0; d < 64; d++) {
            a0 = fmaf(sm[SQF_O + d],      wkr[d],      a0);
            a1 = fmaf(sm[SQF_O + 64 + d], wkr[64 + d], a1);
        }
        sm[SA0_O + tid] = a0; sm[SA1_O + tid] = a1;
        if (bid == 0) {
            g_a0[tid] = a0; g_a1[tid] = a1;
            if (tid < 2) {
                float s = 0.f;
#pragma unroll 16
                for (int d = 0; d < 64; d++)
                    s = fmaf(sm[SQF_O + tid * 64 + d], bk[tid * 64 + d], s);
                g_qbk[tid] = s;
            }
        }
    }
    __syncthreads();

    // contract G with a_h: per-warp slots (no atomics)
    {
        float ar00 = sm[SA0_O + mb + lr],      ar01 = sm[SA0_O + mb + lr + 8];
        float ar02 = sm[SA0_O + mb + 16 + lr], ar03 = sm[SA0_O + mb + 16 + lr + 8];
        float ar10 = sm[SA1_O + mb + lr],      ar11 = sm[SA1_O + mb + lr + 8];
        float ar12 = sm[SA1_O + mb + 16 + lr], ar13 = sm[SA1_O + mb + 16 + lr + 8];
        float* slot = &sm[SLOTV_O + (w >> 1) * 256];
#pragma unroll
        for (int nt = 0; nt < 8; nt++) {
#pragma unroll
            for (int j = 0; j < 2; j++) {
                float s0 = ar00 * g[0][nt][j] + ar01 * g[0][nt][2 + j]
                         + ar02 * g[1][nt][j] + ar03 * g[1][nt][2 + j];
                float s1 = ar10 * g[0][nt][j] + ar11 * g[0][nt][2 + j]
                         + ar12 * g[1][nt][j] + ar13 * g[1][nt][2 + j];
                s0 += __shfl_down_sync(0xFFFFFFFFu, s0, 16);
                s0 += __shfl_down_sync(0xFFFFFFFFu, s0, 8);
                s0 += __shfl_down_sync(0xFFFFFFFFu, s0, 4);
                s1 += __shfl_down_sync(0xFFFFFFFFu, s1, 16);
                s1 += __shfl_down_sync(0xFFFFFFFFu, s1, 8);
                s1 += __shfl_down_sync(0xFFFFFFFFu, s1, 4);
                if (lr == 0) {
                    int col = nb + nt * 8 + 2 * lc + j;
                    slot[col]       = s0;
                    slot[128 + col] = s1;
                }
            }
        }
        // S columns: same slot scheme
        float* slotS = &sm[SLOTS_O + (w >> 1) * 128];
#pragma unroll
        for (int i = 0; i < 16; i++) {
            float v = sacc[i];
            v += __shfl_down_sync(0xFFFFFFFFu, v, 16);
            v += __shfl_down_sync(0xFFFFFFFFu, v, 8);
            v += __shfl_down_sync(0xFFFFFFFFu, v, 4);
            if (lr == 0) slotS[nb + (i >> 1) * 8 + 2 * lc + (i & 1)] = v;
        }
    }
    __syncthreads();

    // final slot reduce -> global partials
    if (tid < 256) {
        float sv = sm[SLOTV_O + tid] + sm[SLOTV_O + 256 + tid]
                 + sm[SLOTV_O + 512 + tid] + sm[SLOTV_O + 768 + tid];
        g_partV[bid][tid] = sv;
    }
    if (tid < 128) {
        float s = sm[SLOTS_O + tid] + sm[SLOTS_O + 128 + tid]
                + sm[SLOTS_O + 256 + tid] + sm[SLOTS_O + 384 + tid];
        g_partS[bid][tid] = s;
    }
}

// ================= tail: 4-way k-split, 512 threads =================
__global__ void tail_kernel(const float* __restrict__ Wv, const float* __restrict__ bv,
                            const float* __restrict__ Wo, const float* __restrict__ bo,
                            float* __restrict__ out)
{
    __shared__ float r3[4][3][DD];
    __shared__ float ss[DD], w0[DD], w1[DD], sa0[DD], sa1[DD], sattn[DD];
    const int t    = threadIdx.x & 127;
    const int part = threadIdx.x >> 7;   // 0..3
    const int b    = blockIdx.x;
    const float qbk0 = g_qbk[0], qbk1 = g_qbk[1];

    // phase 0: partial loads (4-way) + stage a vectors
    r3[part][0][t] = g_partS[b * 4 + part][t];
    r3[part][1][t] = g_partV[b * 4 + part][t];
    r3[part][2][t] = g_partV[b * 4 + part][128 + t];
    if (part == 1) sa0[t] = g_a0[t];
    if (part == 2) sa1[t] = g_a1[t];
    __syncthreads();

    if (part == 0) {
        float S  = r3[0][0][t] + r3[1][0][t] + r3[2][0][t] + r3[3][0][t];
        float V0 = r3[0][1][t] + r3[1][1][t] + r3[2][1][t] + r3[3][1][t];
        float V1 = r3[0][2][t] + r3[1][2][t] + r3[2][2][t] + r3[3][2][t];
        ss[t] = S;
        w0[t] = V0 + qbk0 * S;
        w1[t] = V1 + qbk1 * S;
    }
    __syncthreads();

    // asd_h = a_h . s  (redundant per-thread; smem broadcast)
    float asd0 = 0.f, asd1 = 0.f;
#pragma unroll
    for (int q = 0; q < DD; q++) {
        asd0 = fmaf(sa0[q], ss[q], asd0);
        asd1 = fmaf(sa1[q], ss[q], asd1);
    }

    // y[t] = sum_q w_h[q] * Wv[q][t]  — 4-way split over q
    const int h = t >> 6;
    const float* wh = h ? w1 : w0;
    {
        float yp = 0.f;
        const int q0 = part * 32;
#pragma unroll
        for (int qq = 0; qq < 32; qq++)
            yp = fmaf(wh[q0 + qq], Wv[(q0 + qq) * DD + t], yp);
        r3[part][0][t] = yp;
    }
    __syncthreads();

    if (part == 0) {
        float y = r3[0][0][t] + r3[1][0][t] + r3[2][0][t] + r3[3][0][t];
        float asd = h ? asd1 : asd0;
        float qbk = h ? qbk1 : qbk0;
        sattn[t] = (y + (asd + (float)NN * qbk) * bv[t]) * (1.0f / (float)NN);
    }
    __syncthreads();

    // out = attn @ Wo + bo — 4-way split over i
    {
        float op = 0.f;
        const int i0 = part * 32;
#pragma unroll
        for (int ii = 0; ii < 32; ii++)
            op = fmaf(sattn[i0 + ii], Wo[(i0 + ii) * DD + t], op);
        r3[part][1][t] = op;
    }
    __syncthreads();

    if (part == 0)
        out[b * DD + t] = bo[t] + r3[0][1][t] + r3[1][1][t] + r3[2][1][t] + r3[3][1][t];
}

// ================= launch =================
extern "C" void kernel_launch(void* const* d_in, const int* in_sizes, int n_in,
                              void* d_out, int out_size)
{
    const float* u     = (const float*)d_in[0];
    const float* W1    = (const float*)d_in[2];
    const float* b1    = (const float*)d_in[3];
    const float* W2    = (const float*)d_in[4];
    const float* b2    = (const float*)d_in[5];
    const float* embed = (const float*)d_in[6];
    const float* Wq    = (const float*)d_in[7];
    const float* bq    = (const float*)d_in[8];
    const float* Wk    = (const float*)d_in[9];
    const float* bk    = (const float*)d_in[10];
    const float* Wv    = (const float*)d_in[11];
    const float* bv    = (const float*)d_in[12];
    const float* Wo    = (const float*)d_in[13];
    const float* bo    = (const float*)d_in[14];
    float* out = (float*)d_out;

    cudaFuncSetAttribute(fused_mma_kernel,
                         cudaFuncAttributeMaxDynamicSharedMemorySize, SMEM_BYTES);

    fused_mma_kernel<<<NBLK, 256, SMEM_BYTES>>>(u, W1, b1, W2, b2, embed, Wq, bq, Wk, bk);
    tail_kernel<<<BB, 512>>>(Wv, bv, Wo, bo, out);
}

// round 16
// speedup vs baseline: 3.3520x; 1.7976x over previous
#include <cuda_runtime.h>
#include <cuda_fp16.h>
#include <cstdint>

#define BB 32
#define NN 4096
#define DU 64
#define DD 128
#define TILES 8
#define CHUNKS 4
#define NBLK (BB*CHUNKS)     // 128 blocks, single wave

// ---- shared memory layout ----
// half regions (offsets in halves)
#define H_W1T 0                      // [128 n][72]  W1^T n-major (k pairs contiguous)
#define H_W2T 9216                   // [128 n][136] W2^T n-major
#define H_U   26624                  // [128 tok][72]
#define H_Z1  35840                  // [128 tok][136] token-major
#define H_ZT  53248                  // [128 feat][136] feature-major (end 70656)
// float regions (offsets in floats, from start of smem)
#define F_BASE 35328
#define B1_O   (F_BASE)
#define B2_O   (B1_O + 128)
#define SQF_O  (B2_O + 128)
#define SA0_O  (SQF_O + 128)
#define SA1_O  (SA0_O + 128)
#define SLOTV_O (SA1_O + 128)        // [4][256]
#define SLOTS_O (SLOTV_O + 1024)     // [4][128] (qf half-1 partial at start)
#define SMEM_FLOATS (SLOTS_O + 512)
#define SMEM_BYTES (SMEM_FLOATS * 4) // ~150 KB

__device__ float g_partV[NBLK][256];
__device__ float g_partS[NBLK][DD];
__device__ float g_a0[DD], g_a1[DD];
__device__ float g_qbk[2];

// jax.nn.gelu approximate
static __device__ __forceinline__ float gelu_f(float x) {
    float x2 = x * x;
    float y2 = x * fmaf(0.0713548162f, x2, 1.5957691216f);
    float e  = __expf(y2);
    return x - __fdividef(x, e + 1.0f);
}
// m16n8k16 fp16 HMMA, f32 accum, D = A*B + D
static __device__ __forceinline__ void mma16(float* c, const uint32_t* a, const uint32_t* b) {
    asm volatile(
        "mma.sync.aligned.m16n8k16.row.col.f32.f16.f16.f32 "
        "{%0,%1,%2,%3},{%4,%5,%6,%7},{%8,%9},{%0,%1,%2,%3};"
        : "+f"(c[0]), "+f"(c[1]), "+f"(c[2]), "+f"(c[3])
        : "r"(a[0]), "r"(a[1]), "r"(a[2]), "r"(a[3]), "r"(b[0]), "r"(b[1]));
}
static __device__ __forceinline__ uint32_t h2u(float lo, float hi) {
    __half2 h = __float22half2_rn(make_float2(lo, hi));
    return *(uint32_t*)&h;
}

// ================= main fused kernel =================
__global__ void __launch_bounds__(256, 1)
fused_mma_kernel(const float* __restrict__ u,
                 const float* __restrict__ W1, const float* __restrict__ b1,
                 const float* __restrict__ W2, const float* __restrict__ b2,
                 const float* __restrict__ embed,
                 const float* __restrict__ Wq, const float* __restrict__ bq,
                 const float* __restrict__ Wk, const float* __restrict__ bk)
{
    extern __shared__ float sm[];
    __half* smh = (__half*)sm;
    const int tid  = threadIdx.x;
    const int w    = tid >> 5;
    const int lane = tid & 31;
    const int lr   = lane >> 2;      // fragment row group 0..7
    const int lc   = lane & 3;       // fragment k group 0..3
    const int mb   = (w >> 1) * 32;  // warp row base
    const int nb   = (w & 1) * 64;   // warp col base
    const int bid  = blockIdx.x;

    // ---- stage W1^T (n-major, k-pairs contiguous), fp16 ----
    for (int it = 0; it < 16; it++) {
        int idx = it * 256 + tid;            // 4096 pairs
        int n = idx & 127, kp = idx >> 7;    // kp 0..31
        float w0 = W1[(2 * kp) * DD + n];
        float w1 = W1[(2 * kp + 1) * DD + n];
        *(uint32_t*)&smh[H_W1T + n * 72 + 2 * kp] = h2u(w0, w1);
    }
    // ---- stage W2^T ----
    for (int it = 0; it < 32; it++) {
        int idx = it * 256 + tid;            // 8192 pairs
        int n = idx & 127, kp = idx >> 7;    // kp 0..63
        float w0 = W2[(2 * kp) * DD + n];
        float w1 = W2[(2 * kp + 1) * DD + n];
        *(uint32_t*)&smh[H_W2T + n * 136 + 2 * kp] = h2u(w0, w1);
    }
    if (tid < 128) {
        sm[B1_O + tid] = b1[tid]; sm[B2_O + tid] = b2[tid];
    }
    // qf partial: all 256 threads, 2-way split over p
    {
        const int t = tid & 127, half = tid >> 7;
        const float* wq = Wq + (size_t)(half * 64) * DD + t;
        const float* eb = embed + half * 64;
        float acc = 0.f;
#pragma unroll 8
        for (int p = 0; p < 64; p++) acc = fmaf(eb[p], wq[(size_t)p * DD], acc);
        sm[(half ? SLOTS_O : SQF_O) + t] = acc;
    }

    float g[2][8][4];     // Gram accumulators
#pragma unroll
    for (int mt = 0; mt < 2; mt++)
#pragma unroll
        for (int nt = 0; nt < 8; nt++)
#pragma unroll
            for (int i = 0; i < 4; i++) g[mt][nt][i] = 0.f;
    float sacc[16];
#pragma unroll
    for (int i = 0; i < 16; i++) sacc[i] = 0.f;

    const float* ub = u + ((size_t)(bid >> 2) * NN + (size_t)(bid & 3) * 1024) * DU;

    __syncthreads();

    // combine qf halves (needed only post-loop; later syncs cover visibility)
    if (tid < 128)
        sm[SQF_O + tid] = sm[SQF_O + tid] + sm[SLOTS_O + tid] + bq[tid];

    // per-thread bias copies
    float b1r[16], b2r[16];
#pragma unroll
    for (int nt = 0; nt < 8; nt++) {
        int col = nb + nt * 8 + 2 * lc;
        b1r[nt * 2] = sm[B1_O + col]; b1r[nt * 2 + 1] = sm[B1_O + col + 1];
        b2r[nt * 2] = sm[B2_O + col]; b2r[nt * 2 + 1] = sm[B2_O + col + 1];
    }

    for (int tt = 0; tt < TILES; tt++) {
        // ---- load U tile (128 tok x 64) -> fp16 smem, pitch 72 ----
        {
            const float4* uv = (const float4*)(ub + (size_t)tt * 128 * DU);
#pragma unroll
            for (int i = 0; i < 8; i++) {
                int idx = i * 256 + tid;
                int tok = idx >> 4, kq = idx & 15;
                float4 f = uv[idx];
                uint2 pk = make_uint2(h2u(f.x, f.y), h2u(f.z, f.w));
                *(uint2*)&smh[H_U + tok * 72 + kq * 4] = pk;
            }
        }
        __syncthreads();

        float c[2][8][4];

        // ======== MLP1: C = U @ W1  (K=64, 4 k-steps) ========
#pragma unroll
        for (int mt = 0; mt < 2; mt++)
#pragma unroll
            for (int nt = 0; nt < 8; nt++)
#pragma unroll
                for (int i = 0; i < 4; i++) c[mt][nt][i] = 0.f;
        {
            const __half* As = &smh[H_U + (mb + lr) * 72 + 2 * lc];
            const __half* Bs = &smh[H_W1T + (nb + lr) * 72 + 2 * lc];
#pragma unroll
            for (int kt = 0; kt < 4; kt++) {
                uint32_t a[2][4], bf[8][2];
#pragma unroll
                for (int mt = 0; mt < 2; mt++) {
                    const __half* p = As + mt * 16 * 72 + kt * 16;
                    a[mt][0] = *(const uint32_t*)(p);
                    a[mt][1] = *(const uint32_t*)(p + 8 * 72);
                    a[mt][2] = *(const uint32_t*)(p + 8);
                    a[mt][3] = *(const uint32_t*)(p + 8 * 72 + 8);
                }
#pragma unroll
                for (int nt = 0; nt < 8; nt++) {
                    const __half* p = Bs + nt * 8 * 72 + kt * 16;
                    bf[nt][0] = *(const uint32_t*)(p);
                    bf[nt][1] = *(const uint32_t*)(p + 8);
                }
#pragma unroll
                for (int mt = 0; mt < 2; mt++)
#pragma unroll
                    for (int nt = 0; nt < 8; nt++) mma16(c[mt][nt], a[mt], bf[nt]);
            }
        }
        __syncthreads();

        // epilogue 1: Z1 = gelu(C + b1), token-major fp16
#pragma unroll
        for (int mt = 0; mt < 2; mt++)
#pragma unroll
            for (int nt = 0; nt < 8; nt++) {
                int row = mb + mt * 16 + lr;
                int col = nb + nt * 8 + 2 * lc;
                float z0 = gelu_f(c[mt][nt][0] + b1r[nt * 2]);
                float z1 = gelu_f(c[mt][nt][1] + b1r[nt * 2 + 1]);
                float z2 = gelu_f(c[mt][nt][2] + b1r[nt * 2]);
                float z3 = gelu_f(c[mt][nt][3] + b1r[nt * 2 + 1]);
                *(uint32_t*)&smh[H_Z1 + row * 136 + col]       = h2u(z0, z1);
                *(uint32_t*)&smh[H_Z1 + (row + 8) * 136 + col] = h2u(z2, z3);
            }
        __syncthreads();

        // ======== MLP2: C = Z1 @ W2  (K=128, 8 k-steps) ========
#pragma unroll
        for (int mt = 0; mt < 2; mt++)
#pragma unroll
            for (int nt = 0; nt < 8; nt++)
#pragma unroll
                for (int i = 0; i < 4; i++) c[mt][nt][i] = 0.f;
        {
            const __half* As = &smh[H_Z1 + (mb + lr) * 136 + 2 * lc];
            const __half* Bs = &smh[H_W2T + (nb + lr) * 136 + 2 * lc];
#pragma unroll
            for (int kt = 0; kt < 8; kt++) {
                uint32_t a[2][4], bf[8][2];
#pragma unroll
                for (int mt = 0; mt < 2; mt++) {
                    const __half* p = As + mt * 16 * 136 + kt * 16;
                    a[mt][0] = *(const uint32_t*)(p);
                    a[mt][1] = *(const uint32_t*)(p + 8 * 136);
                    a[mt][2] = *(const uint32_t*)(p + 8);
                    a[mt][3] = *(const uint32_t*)(p + 8 * 136 + 8);
                }
#pragma unroll
                for (int nt = 0; nt < 8; nt++) {
                    const __half* p = Bs + nt * 8 * 136 + kt * 16;
                    bf[nt][0] = *(const uint32_t*)(p);
                    bf[nt][1] = *(const uint32_t*)(p + 8);
                }
#pragma unroll
                for (int mt = 0; mt < 2; mt++)
#pragma unroll
                    for (int nt = 0; nt < 8; nt++) mma16(c[mt][nt], a[mt], bf[nt]);
            }
        }
        __syncthreads();

        // epilogue 2: Z = gelu(C + b2); S += cols; store Z TRANSPOSED (feature-major)
#pragma unroll
        for (int mt = 0; mt < 2; mt++)
#pragma unroll
            for (int nt = 0; nt < 8; nt++) {
                int row = mb + mt * 16 + lr;          // token
                int col = nb + nt * 8 + 2 * lc;       // feature
                float z0 = gelu_f(c[mt][nt][0] + b2r[nt * 2]);
                float z1 = gelu_f(c[mt][nt][1] + b2r[nt * 2 + 1]);
                float z2 = gelu_f(c[mt][nt][2] + b2r[nt * 2]);
                float z3 = gelu_f(c[mt][nt][3] + b2r[nt * 2 + 1]);
                sacc[nt * 2]     += z0 + z2;
                sacc[nt * 2 + 1] += z1 + z3;
                smh[H_ZT + col * 136 + row]           = __float2half_rn(z0);
                smh[H_ZT + (col + 1) * 136 + row]     = __float2half_rn(z1);
                smh[H_ZT + col * 136 + row + 8]       = __float2half_rn(z2);
                smh[H_ZT + (col + 1) * 136 + row + 8] = __float2half_rn(z3);
            }
        __syncthreads();

        // ======== Gram: G += Z^T @ Z  (K=128 tokens, 8 k-steps; both ops from ZT) ========
        {
            const __half* As = &smh[H_ZT + (mb + lr) * 136 + 2 * lc];
            const __half* Bs = &smh[H_ZT + (nb + lr) * 136 + 2 * lc];
#pragma unroll
            for (int kt = 0; kt < 8; kt++) {
                uint32_t a[2][4], bf[8][2];
#pragma unroll
                for (int mt = 0; mt < 2; mt++) {
                    const __half* p = As + mt * 16 * 136 + kt * 16;
                    a[mt][0] = *(const uint32_t*)(p);
                    a[mt][1] = *(const uint32_t*)(p + 8 * 136);
                    a[mt][2] = *(const uint32_t*)(p + 8);
                    a[mt][3] = *(const uint32_t*)(p + 8 * 136 + 8);
                }
#pragma unroll
                for (int nt = 0; nt < 8; nt++) {
                    const __half* p = Bs + nt * 8 * 136 + kt * 16;
                    bf[nt][0] = *(const uint32_t*)(p);
                    bf[nt][1] = *(const uint32_t*)(p + 8);
                }
#pragma unroll
                for (int mt = 0; mt < 2; mt++)
#pragma unroll
                    for (int nt = 0; nt < 8; nt++) mma16(g[mt][nt], a[mt], bf[nt]);
            }
        }
        // no sync needed here: next-tile U staging touches a disjoint region and
        // the U-staging sync orders Gram readers before the next ZT writers
    }
    __syncthreads();

    // ================= post-loop =================
    // stage Wk as fp32 into the dead Z1/ZT half-region, pitch 129 (conflict-free col reads)
    {
        float* zf = (float*)&smh[H_Z1];
        for (int i = tid; i < 128 * 128; i += 256) {
            int r = i >> 7, d = i & 127;
            zf[r * 129 + d] = Wk[i];
        }
    }
    __syncthreads();

    // a_h[p] = sum_d qf[h*64+d] * Wk[p][h*64+d]
    if (tid < 128) {
        const float* zf = (const float*)&smh[H_Z1];
        float a0 = 0.f, a1 = 0.f;
        const float* wkr = &zf[tid * 129];
#pragma unroll 16
        for (int d = 0; d < 64; d++) {
            a0 = fmaf(sm[SQF_O + d],      wkr[d],      a0);
            a1 = fmaf(sm[SQF_O + 64 + d], wkr[64 + d], a1);
        }
        sm[SA0_O + tid] = a0; sm[SA1_O + tid] = a1;
        if (bid == 0) {
            g_a0[tid] = a0; g_a1[tid] = a1;
            if (tid < 2) {
                float s = 0.f;
#pragma unroll 16
                for (int d = 0; d < 64; d++)
                    s = fmaf(sm[SQF_O + tid * 64 + d], bk[tid * 64 + d], s);
                g_qbk[tid] = s;
            }
        }
    }
    __syncthreads();

    // contract G with a_h: per-warp slots (no atomics)
    {
        float ar00 = sm[SA0_O + mb + lr],      ar01 = sm[SA0_O + mb + lr + 8];
        float ar02 = sm[SA0_O + mb + 16 + lr], ar03 = sm[SA0_O + mb + 16 + lr + 8];
        float ar10 = sm[SA1_O + mb + lr],      ar11 = sm[SA1_O + mb + lr + 8];
        float ar12 = sm[SA1_O + mb + 16 + lr], ar13 = sm[SA1_O + mb + 16 + lr + 8];
        float* slot = &sm[SLOTV_O + (w >> 1) * 256];
#pragma unroll
        for (int nt = 0; nt < 8; nt++) {
#pragma unroll
            for (int j = 0; j < 2; j++) {
                float s0 = ar00 * g[0][nt][j] + ar01 * g[0][nt][2 + j]
                         + ar02 * g[1][nt][j] + ar03 * g[1][nt][2 + j];
                float s1 = ar10 * g[0][nt][j] + ar11 * g[0][nt][2 + j]
                         + ar12 * g[1][nt][j] + ar13 * g[1][nt][2 + j];
                s0 += __shfl_down_sync(0xFFFFFFFFu, s0, 16);
                s0 += __shfl_down_sync(0xFFFFFFFFu, s0, 8);
                s0 += __shfl_down_sync(0xFFFFFFFFu, s0, 4);
                s1 += __shfl_down_sync(0xFFFFFFFFu, s1, 16);
                s1 += __shfl_down_sync(0xFFFFFFFFu, s1, 8);
                s1 += __shfl_down_sync(0xFFFFFFFFu, s1, 4);
                if (lr == 0) {
                    int col = nb + nt * 8 + 2 * lc + j;
                    slot[col]       = s0;
                    slot[128 + col] = s1;
                }
            }
        }
        float* slotS = &sm[SLOTS_O + (w >> 1) * 128];
#pragma unroll
        for (int i = 0; i < 16; i++) {
            float v = sacc[i];
            v += __shfl_down_sync(0xFFFFFFFFu, v, 16);
            v += __shfl_down_sync(0xFFFFFFFFu, v, 8);
            v += __shfl_down_sync(0xFFFFFFFFu, v, 4);
            if (lr == 0) slotS[nb + (i >> 1) * 8 + 2 * lc + (i & 1)] = v;
        }
    }
    __syncthreads();

    // final slot reduce -> global partials
    if (tid < 256) {
        float sv = sm[SLOTV_O + tid] + sm[SLOTV_O + 256 + tid]
                 + sm[SLOTV_O + 512 + tid] + sm[SLOTV_O + 768 + tid];
        g_partV[bid][tid] = sv;
    }
    if (tid < 128) {
        float s = sm[SLOTS_O + tid] + sm[SLOTS_O + 128 + tid]
                + sm[SLOTS_O + 256 + tid] + sm[SLOTS_O + 384 + tid];
        g_partS[bid][tid] = s;
    }
}

// ================= tail: 4-way k-split, 512 threads =================
__global__ void tail_kernel(const float* __restrict__ Wv, const float* __restrict__ bv,
                            const float* __restrict__ Wo, const float* __restrict__ bo,
                            float* __restrict__ out)
{
    __shared__ float r3[4][3][DD];
    __shared__ float ss[DD], w0[DD], w1[DD], sa0[DD], sa1[DD], sattn[DD];
    const int t    = threadIdx.x & 127;
    const int part = threadIdx.x >> 7;   // 0..3
    const int b    = blockIdx.x;
    const float qbk0 = g_qbk[0], qbk1 = g_qbk[1];

    r3[part][0][t] = g_partS[b * 4 + part][t];
    r3[part][1][t] = g_partV[b * 4 + part][t];
    r3[part][2][t] = g_partV[b * 4 + part][128 + t];
    if (part == 1) sa0[t] = g_a0[t];
    if (part == 2) sa1[t] = g_a1[t];
    __syncthreads();

    if (part == 0) {
        float S  = r3[0][0][t] + r3[1][0][t] + r3[2][0][t] + r3[3][0][t];
        float V0 = r3[0][1][t] + r3[1][1][t] + r3[2][1][t] + r3[3][1][t];
        float V1 = r3[0][2][t] + r3[1][2][t] + r3[2][2][t] + r3[3][2][t];
        ss[t] = S;
        w0[t] = V0 + qbk0 * S;
        w1[t] = V1 + qbk1 * S;
    }
    __syncthreads();

    float asd0 = 0.f, asd1 = 0.f;
#pragma unroll
    for (int q = 0; q < DD; q++) {
        asd0 = fmaf(sa0[q], ss[q], asd0);
        asd1 = fmaf(sa1[q], ss[q], asd1);
    }

    const int h = t >> 6;
    const float* wh = h ? w1 : w0;
    {
        float yp = 0.f;
        const int q0 = part * 32;
#pragma unroll
        for (int qq = 0; qq < 32; qq++)
            yp = fmaf(wh[q0 + qq], Wv[(q0 + qq) * DD + t], yp);
        r3[part][0][t] = yp;
    }
    __syncthreads();

    if (part == 0) {
        float y = r3[0][0][t] + r3[1][0][t] + r3[2][0][t] + r3[3][0][t];
        float asd = h ? asd1 : asd0;
        float qbk = h ? qbk1 : qbk0;
        sattn[t] = (y + (asd + (float)NN * qbk) * bv[t]) * (1.0f / (float)NN);
    }
    __syncthreads();

    {
        float op = 0.f;
        const int i0 = part * 32;
#pragma unroll
        for (int ii = 0; ii < 32; ii++)
            op = fmaf(sattn[i0 + ii], Wo[(i0 + ii) * DD + t], op);
        r3[part][1][t] = op;
    }
    __syncthreads();

    if (part == 0)
        out[b * DD + t] = bo[t] + r3[0][1][t] + r3[1][1][t] + r3[2][1][t] + r3[3][1][t];
}

// ================= launch =================
extern "C" void kernel_launch(void* const* d_in, const int* in_sizes, int n_in,
                              void* d_out, int out_size)
{
    const float* u     = (const float*)d_in[0];
    const float* W1    = (const float*)d_in[2];
    const float* b1    = (const float*)d_in[3];
    const float* W2    = (const float*)d_in[4];
    const float* b2    = (const float*)d_in[5];
    const float* embed = (const float*)d_in[6];
    const float* Wq    = (const float*)d_in[7];
    const float* bq    = (const float*)d_in[8];
    const float* Wk    = (const float*)d_in[9];
    const float* bk    = (const float*)d_in[10];
    const float* Wv    = (const float*)d_in[11];
    const float* bv    = (const float*)d_in[12];
    const float* Wo    = (const float*)d_in[13];
    const float* bo    = (const float*)d_in[14];
    float* out = (float*)d_out;

    cudaFuncSetAttribute(fused_mma_kernel,
                         cudaFuncAttributeMaxDynamicSharedMemorySize, SMEM_BYTES);

    fused_mma_kernel<<<NBLK, 256, SMEM_BYTES>>>(u, W1, b1, W2, b2, embed, Wq, bq, Wk, bk);
    tail_kernel<<<BB, 512>>>(Wv, bv, Wo, bo, out);
}